// round 8
// baseline (speedup 1.0000x reference)
#include <cuda_runtime.h>
#include <cuda_fp16.h>
#include <cstdint>

// GroupQuerySelfAttention: B=2, S=2048, D=768, NH=12, GH=4 (rep=3), HD=64
// MASK_FILL = -1e-9 => masked P entries == exp(-1e-9) == 1.0f; exact softmax,
// no max subtraction. QKV: single merged tf32-mma GEMM launch writing f16 Q/K
// ([b,h,s,hd]) and f16 V transposed ([b,g,hd,s]) via smem-staged epilogue.
// Attention: all-fp16 mma, 3-stage cp.async pipeline (proven 103 us).
// Out-proj: tf32 GEMM. Buggy merge == attention out stored [B,NH,HD,S].

namespace {
constexpr int kB  = 2;
constexpr int kS  = 2048;
constexpr int kD  = 768;
constexpr int kNH = 12;
constexpr int kGH = 4;
constexpr int kHD = 64;
constexpr int kREP = 3;
constexpr float kScale = 0.125f;
}

__device__ __half g_Qh[(size_t)kB * kNH * kS * kHD];  // [b, h, s, hd]
__device__ __half g_Kh[(size_t)kB * kGH * kS * kHD];  // [b, g, s, hd]
__device__ __half g_Vh[(size_t)kB * kGH * kHD * kS];  // [b, g, hd, s]
__device__ float  g_O [(size_t)kB * kNH * kHD * kS];  // [b, h, hd, q]

// ---------------------------------------------------------------------------
// PTX helpers (baseline — compute_103-family safe)
// ---------------------------------------------------------------------------
__device__ __forceinline__ void mma_tf32(float* d, const uint32_t* a,
                                         uint32_t b0, uint32_t b1) {
    asm volatile(
        "mma.sync.aligned.m16n8k8.row.col.f32.tf32.tf32.f32 "
        "{%0,%1,%2,%3}, {%4,%5,%6,%7}, {%8,%9}, {%0,%1,%2,%3};"
        : "+f"(d[0]), "+f"(d[1]), "+f"(d[2]), "+f"(d[3])
        : "r"(a[0]), "r"(a[1]), "r"(a[2]), "r"(a[3]), "r"(b0), "r"(b1));
}
__device__ __forceinline__ void mma_f16(float* d, const uint32_t* a,
                                        uint32_t b0, uint32_t b1) {
    asm volatile(
        "mma.sync.aligned.m16n8k16.row.col.f32.f16.f16.f32 "
        "{%0,%1,%2,%3}, {%4,%5,%6,%7}, {%8,%9}, {%0,%1,%2,%3};"
        : "+f"(d[0]), "+f"(d[1]), "+f"(d[2]), "+f"(d[3])
        : "r"(a[0]), "r"(a[1]), "r"(a[2]), "r"(a[3]), "r"(b0), "r"(b1));
}
__device__ __forceinline__ uint32_t pack_f16(float lo, float hi) {
    uint32_t r;
    asm("cvt.rn.f16x2.f32 %0, %1, %2;" : "=r"(r) : "f"(hi), "f"(lo));
    return r;
}
__device__ __forceinline__ float rna_tf32(float f) {
    uint32_t r;
    asm("cvt.rna.tf32.f32 %0, %1;" : "=r"(r) : "f"(f));
    return __uint_as_float(r);
}
__device__ __forceinline__ uint32_t smem_u32(const void* p) {
    uint32_t a;
    asm("{ .reg .u64 t; cvta.to.shared.u64 t, %1; cvt.u32.u64 %0, t; }"
        : "=r"(a) : "l"(p));
    return a;
}
__device__ __forceinline__ void cp16(uint32_t dst, const void* src) {
    asm volatile("cp.async.cg.shared.global [%0], [%1], 16;"
                 :: "r"(dst), "l"(src) : "memory");
}
__device__ __forceinline__ void cp_commit() {
    asm volatile("cp.async.commit_group;" ::: "memory");
}
__device__ __forceinline__ void cp_wait1() {
    asm volatile("cp.async.wait_group 1;" ::: "memory");
}

namespace {
constexpr int AST = 36;
constexpr int SMEM_GEMM = (2 * 128 * AST + 2 * 64 * AST) * 4;  // 55296 B
constexpr int TPAD = 136;   // f16 transpose-staging row stride
}

// ---------------------------------------------------------------------------
// Merged QKV projection: C[4096 x 1280] over concatenated {Wq|Wk|Wv} columns.
// CTA tile 128m x 64n, tf32 mma, double-buffered (proven mainloop).
// Epilogues: Q/K -> f16 [b,heads,s,hd]; V -> smem transpose -> f16 [b,g,hd,s]
// with fully coalesced 16B stores.
// ---------------------------------------------------------------------------
__global__ __launch_bounds__(256) void gemm_qkv(
    const float* __restrict__ x,
    const float* __restrict__ Wq, const float* __restrict__ bq,
    const float* __restrict__ Wk, const float* __restrict__ bk,
    const float* __restrict__ Wv, const float* __restrict__ bv)
{
    extern __shared__ float sg[];
    float* As = sg;
    float* Ws = sg + 2 * 128 * AST;

    const int tid = threadIdx.x;
    const int lane = tid & 31;
    const int w = tid >> 5;
    const int lr = lane >> 2;
    const int lc = lane & 3;
    const int rowBase = blockIdx.y * 128;
    const int colBase = blockIdx.x * 64;

    const float* W;
    const float* bias;
    int Nw, colLoc, seg;
    if (colBase < 768)       { W = Wq; bias = bq; Nw = 768; colLoc = colBase;        seg = 0; }
    else if (colBase < 1024) { W = Wk; bias = bk; Nw = 256; colLoc = colBase - 768;  seg = 1; }
    else                     { W = Wv; bias = bv; Nw = 256; colLoc = colBase - 1024; seg = 2; }

    float acc[8][4];
    #pragma unroll
    for (int i = 0; i < 8; ++i)
        #pragma unroll
        for (int j = 0; j < 4; ++j) acc[i][j] = 0.f;

    float4 aL[4], wL[2];
    auto load_chunk = [&](int k0) {
        #pragma unroll
        for (int j = 0; j < 4; ++j) {
            const int fid = tid + 256 * j;
            const int r = fid >> 3, k4 = fid & 7;
            aL[j] = *reinterpret_cast<const float4*>(
                x + (size_t)(rowBase + r) * kD + k0 + k4 * 4);
        }
        #pragma unroll
        for (int j = 0; j < 2; ++j) {
            const int fid = tid + 256 * j;
            const int k = fid >> 4, n4 = fid & 15;
            wL[j] = *reinterpret_cast<const float4*>(
                W + (size_t)(k0 + k) * Nw + colLoc + n4 * 4);
        }
    };
    auto store_chunk = [&](int buf) {
        float* Ab = As + buf * 128 * AST;
        float* Wb = Ws + buf * 64 * AST;
        #pragma unroll
        for (int j = 0; j < 4; ++j) {
            const int fid = tid + 256 * j;
            const int r = fid >> 3, k4 = fid & 7;
            float* d = Ab + r * AST + k4 * 4;
            d[0] = rna_tf32(aL[j].x); d[1] = rna_tf32(aL[j].y);
            d[2] = rna_tf32(aL[j].z); d[3] = rna_tf32(aL[j].w);
        }
        #pragma unroll
        for (int j = 0; j < 2; ++j) {
            const int fid = tid + 256 * j;
            const int k = fid >> 4, n4 = fid & 15;
            Wb[(n4 * 4 + 0) * AST + k] = rna_tf32(wL[j].x);
            Wb[(n4 * 4 + 1) * AST + k] = rna_tf32(wL[j].y);
            Wb[(n4 * 4 + 2) * AST + k] = rna_tf32(wL[j].z);
            Wb[(n4 * 4 + 3) * AST + k] = rna_tf32(wL[j].w);
        }
    };

    load_chunk(0);
    store_chunk(0);
    __syncthreads();

    const int nch = kD / 32;   // 24
    for (int ch = 0; ch < nch; ++ch) {
        if (ch + 1 < nch) load_chunk((ch + 1) * 32);

        const float* Ab = As + (ch & 1) * 128 * AST;
        const float* Wb = Ws + (ch & 1) * 64 * AST;
        const int r0 = w * 16 + lr;
        #pragma unroll
        for (int ks = 0; ks < 4; ++ks) {
            uint32_t a[4];
            a[0] = __float_as_uint(Ab[r0 * AST + ks * 8 + lc]);
            a[1] = __float_as_uint(Ab[(r0 + 8) * AST + ks * 8 + lc]);
            a[2] = __float_as_uint(Ab[r0 * AST + ks * 8 + lc + 4]);
            a[3] = __float_as_uint(Ab[(r0 + 8) * AST + ks * 8 + lc + 4]);
            #pragma unroll
            for (int nf = 0; nf < 8; ++nf) {
                const float* wrow = Wb + (nf * 8 + lr) * AST;
                const uint32_t b0 = __float_as_uint(wrow[ks * 8 + lc]);
                const uint32_t b1 = __float_as_uint(wrow[ks * 8 + lc + 4]);
                mma_tf32(acc[nf], a, b0, b1);
            }
        }

        if (ch + 1 < nch) store_chunk((ch + 1) & 1);
        __syncthreads();
    }

    const int bb = rowBase / kS;             // 128-row tile never crosses batch
    const int s0 = rowBase - bb * kS;

    if (seg == 2) {
        // V: transpose via smem, then coalesced [hd][s] stores
        __half* T = reinterpret_cast<__half*>(sg);   // [64][TPAD]
        #pragma unroll
        for (int half = 0; half < 2; ++half) {
            const int r = w * 16 + lr + half * 8;    // tile row (s index)
            #pragma unroll
            for (int nf = 0; nf < 8; ++nf) {
                const int c = nf * 8 + 2 * lc;
                T[(c + 0) * TPAD + r] = __float2half_rn(acc[nf][half * 2 + 0] + bias[colLoc + c]);
                T[(c + 1) * TPAD + r] = __float2half_rn(acc[nf][half * 2 + 1] + bias[colLoc + c + 1]);
            }
        }
        __syncthreads();
        const int g = colLoc / kHD;
        __half* base = g_Vh + (size_t)(bb * kGH + g) * kHD * kS;
        #pragma unroll
        for (int j = 0; j < 4; ++j) {
            const int idx = tid + 256 * j;           // 1024 uint4 chunks
            const int hd = idx >> 4, ch8 = (idx & 15) * 8;
            uint4 v = *reinterpret_cast<const uint4*>(T + hd * TPAD + ch8);
            *reinterpret_cast<uint4*>(base + (size_t)hd * kS + s0 + ch8) = v;
        }
    } else {
        __half* out = (seg == 0) ? g_Qh : g_Kh;
        const int heads = (seg == 0) ? kNH : kGH;
        #pragma unroll
        for (int half = 0; half < 2; ++half) {
            const int s = s0 + w * 16 + lr + half * 8;
            #pragma unroll
            for (int nf = 0; nf < 8; ++nf) {
                const int c = colLoc + nf * 8 + 2 * lc;
                const int h = c / kHD, cc = c - h * kHD;
                const float v0 = acc[nf][half * 2 + 0] + bias[c];
                const float v1 = acc[nf][half * 2 + 1] + bias[c + 1];
                __half* dst = out + ((size_t)(bb * heads + h) * kS + s) * kHD + cc;
                *reinterpret_cast<uint32_t*>(dst) = pack_f16(v0, v1);
            }
        }
    }
}

// ---------------------------------------------------------------------------
// Out-projection: C[4096 x 768] = g_O @ Wo + bo -> d_out (f32 row-major)
// ---------------------------------------------------------------------------
__global__ __launch_bounds__(256) void gemm_out(
    const float* __restrict__ A, const float* __restrict__ W,
    const float* __restrict__ bias, float* __restrict__ out)
{
    extern __shared__ float sg[];
    float* As = sg;
    float* Ws = sg + 2 * 128 * AST;

    const int tid = threadIdx.x;
    const int lane = tid & 31;
    const int w = tid >> 5;
    const int lr = lane >> 2;
    const int lc = lane & 3;
    const int rowBase = blockIdx.y * 128;
    const int colBase = blockIdx.x * 64;

    float acc[8][4];
    #pragma unroll
    for (int i = 0; i < 8; ++i)
        #pragma unroll
        for (int j = 0; j < 4; ++j) acc[i][j] = 0.f;

    float4 aL[4], wL[2];
    auto load_chunk = [&](int k0) {
        #pragma unroll
        for (int j = 0; j < 4; ++j) {
            const int fid = tid + 256 * j;
            const int r = fid >> 3, k4 = fid & 7;
            aL[j] = *reinterpret_cast<const float4*>(
                A + (size_t)(rowBase + r) * kD + k0 + k4 * 4);
        }
        #pragma unroll
        for (int j = 0; j < 2; ++j) {
            const int fid = tid + 256 * j;
            const int k = fid >> 4, n4 = fid & 15;
            wL[j] = *reinterpret_cast<const float4*>(
                W + (size_t)(k0 + k) * kD + colBase + n4 * 4);
        }
    };
    auto store_chunk = [&](int buf) {
        float* Ab = As + buf * 128 * AST;
        float* Wb = Ws + buf * 64 * AST;
        #pragma unroll
        for (int j = 0; j < 4; ++j) {
            const int fid = tid + 256 * j;
            const int r = fid >> 3, k4 = fid & 7;
            float* d = Ab + r * AST + k4 * 4;
            d[0] = rna_tf32(aL[j].x); d[1] = rna_tf32(aL[j].y);
            d[2] = rna_tf32(aL[j].z); d[3] = rna_tf32(aL[j].w);
        }
        #pragma unroll
        for (int j = 0; j < 2; ++j) {
            const int fid = tid + 256 * j;
            const int k = fid >> 4, n4 = fid & 15;
            Wb[(n4 * 4 + 0) * AST + k] = rna_tf32(wL[j].x);
            Wb[(n4 * 4 + 1) * AST + k] = rna_tf32(wL[j].y);
            Wb[(n4 * 4 + 2) * AST + k] = rna_tf32(wL[j].z);
            Wb[(n4 * 4 + 3) * AST + k] = rna_tf32(wL[j].w);
        }
    };

    load_chunk(0);
    store_chunk(0);
    __syncthreads();

    const int nch = kD / 32;
    for (int ch = 0; ch < nch; ++ch) {
        if (ch + 1 < nch) load_chunk((ch + 1) * 32);
        const float* Ab = As + (ch & 1) * 128 * AST;
        const float* Wb = Ws + (ch & 1) * 64 * AST;
        const int r0 = w * 16 + lr;
        #pragma unroll
        for (int ks = 0; ks < 4; ++ks) {
            uint32_t a[4];
            a[0] = __float_as_uint(Ab[r0 * AST + ks * 8 + lc]);
            a[1] = __float_as_uint(Ab[(r0 + 8) * AST + ks * 8 + lc]);
            a[2] = __float_as_uint(Ab[r0 * AST + ks * 8 + lc + 4]);
            a[3] = __float_as_uint(Ab[(r0 + 8) * AST + ks * 8 + lc + 4]);
            #pragma unroll
            for (int nf = 0; nf < 8; ++nf) {
                const float* wrow = Wb + (nf * 8 + lr) * AST;
                const uint32_t b0 = __float_as_uint(wrow[ks * 8 + lc]);
                const uint32_t b1 = __float_as_uint(wrow[ks * 8 + lc + 4]);
                mma_tf32(acc[nf], a, b0, b1);
            }
        }
        if (ch + 1 < nch) store_chunk((ch + 1) & 1);
        __syncthreads();
    }

    #pragma unroll
    for (int half = 0; half < 2; ++half) {
        const int r = rowBase + w * 16 + lr + half * 8;
        #pragma unroll
        for (int nf = 0; nf < 8; ++nf) {
            const int c = colBase + nf * 8 + 2 * lc;
            float* dst = out + (size_t)r * kD + c;
            dst[0] = acc[nf][half * 2 + 0] + bias[c];
            dst[1] = acc[nf][half * 2 + 1] + bias[c + 1];
        }
    }
}

// ---------------------------------------------------------------------------
// Pipelined all-fp16 attention (unchanged from R7 — proven 103 us / 5.3e-4)
// ---------------------------------------------------------------------------
namespace {
constexpr int KST2 = 72;
constexpr int TILE_B = 64 * KST2 * 2;          // 9216 B
constexpr int STAGE_B = 2 * TILE_B;            // 18432 B
constexpr int SMEM_ATTN = 3 * STAGE_B;         // 55296 B
constexpr int NKT = kS / 64;                   // 32
}

__global__ __launch_bounds__(256, 2) void attn_mma()
{
    extern __shared__ char smem[];
    const uint32_t sb = smem_u32(smem);

    const int tid = threadIdx.x;
    const int lane = tid & 31;
    const int w = tid >> 5;
    const int qt = blockIdx.x, h = blockIdx.y, b = blockIdx.z;
    const int g = h / kREP;
    const int lr = lane >> 2;
    const int lc = lane & 3;

    const __half* Qp = g_Qh + ((size_t)(b * kNH + h) * kS + (size_t)qt * 128) * kHD;
    const __half* Kp = g_Kh + (size_t)(b * kGH + g) * kS * kHD;
    const __half* Vp = g_Vh + (size_t)(b * kGH + g) * kHD * kS;

    auto stage_tile = [&](int kt, int s) {
        const __half* Kt = Kp + (size_t)kt * 64 * kHD;
        const __half* Vt = Vp + (size_t)kt * 64;
        const uint32_t kb = sb + s * STAGE_B;
        const uint32_t vb = kb + TILE_B;
        #pragma unroll
        for (int j = 0; j < 2; ++j) {
            const int c = tid + 256 * j;
            const int r = c >> 3, c8 = (c & 7) * 8;
            const uint32_t off = (uint32_t)(r * KST2 + c8) * 2;
            cp16(kb + off, Kt + (size_t)r * kHD + c8);
            cp16(vb + off, Vt + (size_t)r * kS + c8);
        }
        cp_commit();
    };

    stage_tile(0, 0);
    stage_tile(1, 1);

    __half* Qs = reinterpret_cast<__half*>(smem + 2 * STAGE_B);
    #pragma unroll
    for (int j = 0; j < 4; ++j) {
        const int c = tid + 256 * j;
        const int r = c >> 3, c8 = (c & 7) * 8;
        uint4 v = *reinterpret_cast<const uint4*>(Qp + (size_t)r * kHD + c8);
        *reinterpret_cast<uint4*>(Qs + r * KST2 + c8) = v;
    }
    __syncthreads();

    uint32_t qa[4][4];
    {
        const int r0 = w * 16 + lr;
        #pragma unroll
        for (int ks = 0; ks < 4; ++ks) {
            const int cb = ks * 16 + 2 * lc;
            qa[ks][0] = *reinterpret_cast<const uint32_t*>(Qs + r0 * KST2 + cb);
            qa[ks][1] = *reinterpret_cast<const uint32_t*>(Qs + (r0 + 8) * KST2 + cb);
            qa[ks][2] = *reinterpret_cast<const uint32_t*>(Qs + r0 * KST2 + cb + 8);
            qa[ks][3] = *reinterpret_cast<const uint32_t*>(Qs + (r0 + 8) * KST2 + cb + 8);
        }
    }

    float oacc[8][4];
    #pragma unroll
    for (int i = 0; i < 8; ++i)
        #pragma unroll
        for (int j = 0; j < 4; ++j) oacc[i][j] = 0.f;
    float lsum0 = 0.f, lsum1 = 0.f;
    const int q0 = qt * 128 + w * 16 + lr;

    int buf = 0;
    for (int kt = 0; kt < NKT; ++kt) {
        cp_wait1();
        __syncthreads();

        const __half* Kb = reinterpret_cast<const __half*>(smem + buf * STAGE_B);
        const __half* Vb = Kb + 64 * KST2;

        #pragma unroll
        for (int sub = 0; sub < 2; ++sub) {
            float sacc[4][4];
            #pragma unroll
            for (int i = 0; i < 4; ++i)
                #pragma unroll
                for (int j = 0; j < 4; ++j) sacc[i][j] = 0.f;

            #pragma unroll
            for (int nf = 0; nf < 4; ++nf) {
                const __half* krow = Kb + (sub * 32 + nf * 8 + lr) * KST2;
                #pragma unroll
                for (int ks = 0; ks < 4; ++ks) {
                    const uint32_t b0 = *reinterpret_cast<const uint32_t*>(krow + ks * 16 + 2 * lc);
                    const uint32_t b1 = *reinterpret_cast<const uint32_t*>(krow + ks * 16 + 2 * lc + 8);
                    mma_f16(sacc[nf], qa[ks], b0, b1);
                }
            }

            uint32_t pa[2][4];
            #pragma unroll
            for (int nf = 0; nf < 4; ++nf) {
                const int colb = kt * 64 + sub * 32 + nf * 8 + 2 * lc;
                const float p0 = (colb     <= q0)     ? __expf(sacc[nf][0] * kScale) : 1.0f;
                const float p1 = (colb + 1 <= q0)     ? __expf(sacc[nf][1] * kScale) : 1.0f;
                const float p2 = (colb     <= q0 + 8) ? __expf(sacc[nf][2] * kScale) : 1.0f;
                const float p3 = (colb + 1 <= q0 + 8) ? __expf(sacc[nf][3] * kScale) : 1.0f;
                lsum0 += p0 + p1;
                lsum1 += p2 + p3;
                const int kk = nf >> 1;
                if ((nf & 1) == 0) {
                    pa[kk][0] = pack_f16(p0, p1);
                    pa[kk][1] = pack_f16(p2, p3);
                } else {
                    pa[kk][2] = pack_f16(p0, p1);
                    pa[kk][3] = pack_f16(p2, p3);
                }
            }

            #pragma unroll
            for (int nd = 0; nd < 8; ++nd) {
                const __half* vrow = Vb + (nd * 8 + lr) * KST2 + sub * 32;
                #pragma unroll
                for (int kk = 0; kk < 2; ++kk) {
                    const uint32_t b0 = *reinterpret_cast<const uint32_t*>(vrow + kk * 16 + 2 * lc);
                    const uint32_t b1 = *reinterpret_cast<const uint32_t*>(vrow + kk * 16 + 2 * lc + 8);
                    mma_f16(oacc[nd], pa[kk], b0, b1);
                }
            }
        }

        if (kt + 2 < NKT) {
            stage_tile(kt + 2, (buf + 2) % 3);
        } else {
            cp_commit();
        }
        buf = (buf + 1) % 3;
    }

    lsum0 += __shfl_xor_sync(0xffffffffu, lsum0, 1);
    lsum0 += __shfl_xor_sync(0xffffffffu, lsum0, 2);
    lsum1 += __shfl_xor_sync(0xffffffffu, lsum1, 1);
    lsum1 += __shfl_xor_sync(0xffffffffu, lsum1, 2);
    const float inv0 = 1.f / lsum0;
    const float inv1 = 1.f / lsum1;

    float* Op = g_O + (size_t)(b * kNH + h) * kHD * kS;
    #pragma unroll
    for (int nd = 0; nd < 8; ++nd) {
        const int hd = nd * 8 + 2 * lc;
        Op[(size_t)hd * kS + q0]           = oacc[nd][0] * inv0;
        Op[(size_t)(hd + 1) * kS + q0]     = oacc[nd][1] * inv0;
        Op[(size_t)hd * kS + q0 + 8]       = oacc[nd][2] * inv1;
        Op[(size_t)(hd + 1) * kS + q0 + 8] = oacc[nd][3] * inv1;
    }
}

extern "C" void kernel_launch(void* const* d_in, const int* in_sizes, int n_in,
                              void* d_out, int out_size)
{
    (void)in_sizes; (void)n_in; (void)out_size;
    const float* x  = (const float*)d_in[0];
    const float* Wq = (const float*)d_in[2];
    const float* bq = (const float*)d_in[3];
    const float* Wk = (const float*)d_in[4];
    const float* bk = (const float*)d_in[5];
    const float* Wv = (const float*)d_in[6];
    const float* bv = (const float*)d_in[7];
    const float* Wo = (const float*)d_in[8];
    const float* bo = (const float*)d_in[9];
    float* out = (float*)d_out;

    void* op;
    cudaGetSymbolAddress(&op, g_O);

    cudaFuncSetAttribute(attn_mma, cudaFuncAttributeMaxDynamicSharedMemorySize, SMEM_ATTN);
    cudaFuncSetAttribute(gemm_qkv, cudaFuncAttributeMaxDynamicSharedMemorySize, SMEM_GEMM);
    cudaFuncSetAttribute(gemm_out, cudaFuncAttributeMaxDynamicSharedMemorySize, SMEM_GEMM);

    // merged QKV projection: 1280 concatenated columns, 640 CTAs
    gemm_qkv<<<dim3(1280 / 64, (kB * kS) / 128), 256, SMEM_GEMM>>>(
        x, Wq, bq, Wk, bk, Wv, bv);

    attn_mma<<<dim3(kS / 128, kNH, kB), 256, SMEM_ATTN>>>();

    gemm_out<<<dim3(kD / 64, (kB * kS) / 128), 256, SMEM_GEMM>>>(
        (const float*)op, Wo, bo, out);
}

// round 9
// speedup vs baseline: 1.2438x; 1.2438x over previous
#include <cuda_runtime.h>
#include <cuda_fp16.h>
#include <cstdint>

// GroupQuerySelfAttention: B=2, S=2048, D=768, NH=12, GH=4 (rep=3), HD=64
// MASK_FILL = -1e-9 => masked P entries == exp(-1e-9) == 1.0f; exact softmax,
// no max subtraction. All GEMMs on fp16 mma (same 10-bit RNE mantissa as
// tf32-rna => identical rounding error, half the LDS + mma instructions).
// QKV merged launch writes f16 Q/K [b,h,s,hd] and V^T [b,g,hd,s].
// Attention: all-fp16 mma, 3-stage cp.async pipeline (proven 103 us).
// Buggy merge == attention out stored [B,NH,HD,S].

namespace {
constexpr int kB  = 2;
constexpr int kS  = 2048;
constexpr int kD  = 768;
constexpr int kNH = 12;
constexpr int kGH = 4;
constexpr int kHD = 64;
constexpr int kREP = 3;
constexpr float kScale = 0.125f;
}

__device__ __half g_Qh[(size_t)kB * kNH * kS * kHD];  // [b, h, s, hd]
__device__ __half g_Kh[(size_t)kB * kGH * kS * kHD];  // [b, g, s, hd]
__device__ __half g_Vh[(size_t)kB * kGH * kHD * kS];  // [b, g, hd, s]
__device__ float  g_O [(size_t)kB * kNH * kHD * kS];  // [b, h, hd, q]

// ---------------------------------------------------------------------------
// PTX helpers (baseline — compute_103-family safe)
// ---------------------------------------------------------------------------
__device__ __forceinline__ void mma_f16(float* d, const uint32_t* a,
                                        uint32_t b0, uint32_t b1) {
    asm volatile(
        "mma.sync.aligned.m16n8k16.row.col.f32.f16.f16.f32 "
        "{%0,%1,%2,%3}, {%4,%5,%6,%7}, {%8,%9}, {%0,%1,%2,%3};"
        : "+f"(d[0]), "+f"(d[1]), "+f"(d[2]), "+f"(d[3])
        : "r"(a[0]), "r"(a[1]), "r"(a[2]), "r"(a[3]), "r"(b0), "r"(b1));
}
__device__ __forceinline__ uint32_t pack_f16(float lo, float hi) {
    uint32_t r;
    asm("cvt.rn.f16x2.f32 %0, %1, %2;" : "=r"(r) : "f"(hi), "f"(lo));
    return r;
}
__device__ __forceinline__ uint32_t smem_u32(const void* p) {
    uint32_t a;
    asm("{ .reg .u64 t; cvta.to.shared.u64 t, %1; cvt.u32.u64 %0, t; }"
        : "=r"(a) : "l"(p));
    return a;
}
__device__ __forceinline__ void cp16(uint32_t dst, const void* src) {
    asm volatile("cp.async.cg.shared.global [%0], [%1], 16;"
                 :: "r"(dst), "l"(src) : "memory");
}
__device__ __forceinline__ void cp_commit() {
    asm volatile("cp.async.commit_group;" ::: "memory");
}
__device__ __forceinline__ void cp_wait1() {
    asm volatile("cp.async.wait_group 1;" ::: "memory");
}

// ---------------------------------------------------------------------------
// fp16 GEMM core: CTA tile 128m x 64n, 8 warps (16m x 64n each), K-chunks of
// 32 (two m16n8k16 steps), double-buffered f16 smem. Every fragment reg is a
// single LDS.32. A and W converted f32->f16 at the STS.
// ---------------------------------------------------------------------------
namespace {
constexpr int ASTH = 40;                                 // f16 units / smem row
constexpr int SMEM_GEMM = (2 * 128 * ASTH + 2 * 64 * ASTH) * 2;  // 30720 B
constexpr int TPAD = 136;                                // V-transpose staging
}

struct GemmCore {
    float acc[8][4];
    float4 aL[4], wL[2];
    __half* As;
    __half* Ws;
    const float* A;
    const float* W;
    int Nw, colLoc, rowBase, tid;

    __device__ __forceinline__ void init(__half* sm, const float* A_,
                                         const float* W_, int Nw_, int colLoc_,
                                         int rowBase_, int tid_) {
        As = sm; Ws = sm + 2 * 128 * ASTH;
        A = A_; W = W_; Nw = Nw_; colLoc = colLoc_; rowBase = rowBase_; tid = tid_;
        #pragma unroll
        for (int i = 0; i < 8; ++i)
            #pragma unroll
            for (int j = 0; j < 4; ++j) acc[i][j] = 0.f;
    }
    __device__ __forceinline__ void load_chunk(int k0) {
        #pragma unroll
        for (int j = 0; j < 4; ++j) {
            const int fid = tid + 256 * j;
            const int r = fid >> 3, k4 = fid & 7;
            aL[j] = *reinterpret_cast<const float4*>(
                A + (size_t)(rowBase + r) * kD + k0 + k4 * 4);
        }
        #pragma unroll
        for (int j = 0; j < 2; ++j) {
            const int fid = tid + 256 * j;
            const int k = fid >> 4, n4 = fid & 15;
            wL[j] = *reinterpret_cast<const float4*>(
                W + (size_t)(k0 + k) * Nw + colLoc + n4 * 4);
        }
    }
    __device__ __forceinline__ void store_chunk(int buf) {
        __half* Ab = As + buf * 128 * ASTH;
        __half* Wb = Ws + buf * 64 * ASTH;
        #pragma unroll
        for (int j = 0; j < 4; ++j) {
            const int fid = tid + 256 * j;
            const int r = fid >> 3, k4 = fid & 7;
            uint2 p;
            p.x = pack_f16(aL[j].x, aL[j].y);
            p.y = pack_f16(aL[j].z, aL[j].w);
            *reinterpret_cast<uint2*>(Ab + r * ASTH + k4 * 4) = p;
        }
        #pragma unroll
        for (int j = 0; j < 2; ++j) {
            const int fid = tid + 256 * j;
            const int k = fid >> 4, n4 = fid & 15;
            Wb[(n4 * 4 + 0) * ASTH + k] = __float2half_rn(wL[j].x);
            Wb[(n4 * 4 + 1) * ASTH + k] = __float2half_rn(wL[j].y);
            Wb[(n4 * 4 + 2) * ASTH + k] = __float2half_rn(wL[j].z);
            Wb[(n4 * 4 + 3) * ASTH + k] = __float2half_rn(wL[j].w);
        }
    }
    __device__ __forceinline__ void mainloop(int w, int lr, int lc) {
        load_chunk(0);
        store_chunk(0);
        __syncthreads();
        const int nch = kD / 32;   // 24
        const int r0 = w * 16 + lr;
        for (int ch = 0; ch < nch; ++ch) {
            if (ch + 1 < nch) load_chunk((ch + 1) * 32);
            const __half* Ab = As + (ch & 1) * 128 * ASTH;
            const __half* Wb = Ws + (ch & 1) * 64 * ASTH;
            #pragma unroll
            for (int ks = 0; ks < 2; ++ks) {
                uint32_t a[4];
                const int cb = ks * 16 + 2 * lc;
                a[0] = *reinterpret_cast<const uint32_t*>(Ab + r0 * ASTH + cb);
                a[1] = *reinterpret_cast<const uint32_t*>(Ab + (r0 + 8) * ASTH + cb);
                a[2] = *reinterpret_cast<const uint32_t*>(Ab + r0 * ASTH + cb + 8);
                a[3] = *reinterpret_cast<const uint32_t*>(Ab + (r0 + 8) * ASTH + cb + 8);
                #pragma unroll
                for (int nf = 0; nf < 8; ++nf) {
                    const __half* wrow = Wb + (nf * 8 + lr) * ASTH;
                    const uint32_t b0 = *reinterpret_cast<const uint32_t*>(wrow + cb);
                    const uint32_t b1 = *reinterpret_cast<const uint32_t*>(wrow + cb + 8);
                    mma_f16(acc[nf], a, b0, b1);
                }
            }
            if (ch + 1 < nch) store_chunk((ch + 1) & 1);
            __syncthreads();
        }
    }
};

// ---------------------------------------------------------------------------
// Merged QKV projection (fp16 mma). Columns 0..767 -> Q, 768..1023 -> K,
// 1024..1279 -> V (transposed epilogue via smem).
// ---------------------------------------------------------------------------
__global__ __launch_bounds__(256) void gemm_qkv(
    const float* __restrict__ x,
    const float* __restrict__ Wq, const float* __restrict__ bq,
    const float* __restrict__ Wk, const float* __restrict__ bk,
    const float* __restrict__ Wv, const float* __restrict__ bv)
{
    extern __shared__ char smraw[];
    __half* sm = reinterpret_cast<__half*>(smraw);

    const int tid = threadIdx.x;
    const int lane = tid & 31;
    const int w = tid >> 5;
    const int lr = lane >> 2;
    const int lc = lane & 3;
    const int rowBase = blockIdx.y * 128;
    const int colBase = blockIdx.x * 64;

    const float* W;
    const float* bias;
    int Nw, colLoc, seg;
    if (colBase < 768)       { W = Wq; bias = bq; Nw = 768; colLoc = colBase;        seg = 0; }
    else if (colBase < 1024) { W = Wk; bias = bk; Nw = 256; colLoc = colBase - 768;  seg = 1; }
    else                     { W = Wv; bias = bv; Nw = 256; colLoc = colBase - 1024; seg = 2; }

    GemmCore core;
    core.init(sm, x, W, Nw, colLoc, rowBase, tid);
    core.mainloop(w, lr, lc);

    const int bb = rowBase / kS;
    const int s0 = rowBase - bb * kS;

    if (seg == 2) {
        __half* T = sm;   // [64][TPAD] staging (post-mainloop, sync'd)
        #pragma unroll
        for (int half = 0; half < 2; ++half) {
            const int r = w * 16 + lr + half * 8;
            #pragma unroll
            for (int nf = 0; nf < 8; ++nf) {
                const int c = nf * 8 + 2 * lc;
                T[(c + 0) * TPAD + r] = __float2half_rn(core.acc[nf][half * 2 + 0] + bias[colLoc + c]);
                T[(c + 1) * TPAD + r] = __float2half_rn(core.acc[nf][half * 2 + 1] + bias[colLoc + c + 1]);
            }
        }
        __syncthreads();
        const int g = colLoc / kHD;
        __half* base = g_Vh + (size_t)(bb * kGH + g) * kHD * kS;
        #pragma unroll
        for (int j = 0; j < 4; ++j) {
            const int idx = tid + 256 * j;
            const int hd = idx >> 4, ch8 = (idx & 15) * 8;
            uint4 v = *reinterpret_cast<const uint4*>(T + hd * TPAD + ch8);
            *reinterpret_cast<uint4*>(base + (size_t)hd * kS + s0 + ch8) = v;
        }
    } else {
        __half* out = (seg == 0) ? g_Qh : g_Kh;
        const int heads = (seg == 0) ? kNH : kGH;
        #pragma unroll
        for (int half = 0; half < 2; ++half) {
            const int s = s0 + w * 16 + lr + half * 8;
            #pragma unroll
            for (int nf = 0; nf < 8; ++nf) {
                const int c = colLoc + nf * 8 + 2 * lc;
                const int h = c / kHD, cc = c - h * kHD;
                const float v0 = core.acc[nf][half * 2 + 0] + bias[c];
                const float v1 = core.acc[nf][half * 2 + 1] + bias[c + 1];
                __half* dst = out + ((size_t)(bb * heads + h) * kS + s) * kHD + cc;
                *reinterpret_cast<uint32_t*>(dst) = pack_f16(v0, v1);
            }
        }
    }
}

// ---------------------------------------------------------------------------
// Out-projection (fp16 mma): C[4096 x 768] = g_O @ Wo + bo -> f32 row-major
// ---------------------------------------------------------------------------
__global__ __launch_bounds__(256) void gemm_out(
    const float* __restrict__ A, const float* __restrict__ W,
    const float* __restrict__ bias, float* __restrict__ out)
{
    extern __shared__ char smraw[];
    __half* sm = reinterpret_cast<__half*>(smraw);

    const int tid = threadIdx.x;
    const int lane = tid & 31;
    const int w = tid >> 5;
    const int lr = lane >> 2;
    const int lc = lane & 3;
    const int rowBase = blockIdx.y * 128;
    const int colBase = blockIdx.x * 64;

    GemmCore core;
    core.init(sm, A, W, kD, colBase, rowBase, tid);
    core.mainloop(w, lr, lc);

    #pragma unroll
    for (int half = 0; half < 2; ++half) {
        const int r = rowBase + w * 16 + lr + half * 8;
        #pragma unroll
        for (int nf = 0; nf < 8; ++nf) {
            const int c = colBase + nf * 8 + 2 * lc;
            float* dst = out + (size_t)r * kD + c;
            dst[0] = core.acc[nf][half * 2 + 0] + bias[c];
            dst[1] = core.acc[nf][half * 2 + 1] + bias[c + 1];
        }
    }
}

// ---------------------------------------------------------------------------
// Pipelined all-fp16 attention (unchanged — proven 103 us / 5.3e-4)
// ---------------------------------------------------------------------------
namespace {
constexpr int KST2 = 72;
constexpr int TILE_B = 64 * KST2 * 2;          // 9216 B
constexpr int STAGE_B = 2 * TILE_B;            // 18432 B
constexpr int SMEM_ATTN = 3 * STAGE_B;         // 55296 B
constexpr int NKT = kS / 64;                   // 32
}

__global__ __launch_bounds__(256, 2) void attn_mma()
{
    extern __shared__ char smem[];
    const uint32_t sb = smem_u32(smem);

    const int tid = threadIdx.x;
    const int lane = tid & 31;
    const int w = tid >> 5;
    const int qt = blockIdx.x, h = blockIdx.y, b = blockIdx.z;
    const int g = h / kREP;
    const int lr = lane >> 2;
    const int lc = lane & 3;

    const __half* Qp = g_Qh + ((size_t)(b * kNH + h) * kS + (size_t)qt * 128) * kHD;
    const __half* Kp = g_Kh + (size_t)(b * kGH + g) * kS * kHD;
    const __half* Vp = g_Vh + (size_t)(b * kGH + g) * kHD * kS;

    auto stage_tile = [&](int kt, int s) {
        const __half* Kt = Kp + (size_t)kt * 64 * kHD;
        const __half* Vt = Vp + (size_t)kt * 64;
        const uint32_t kb = sb + s * STAGE_B;
        const uint32_t vb = kb + TILE_B;
        #pragma unroll
        for (int j = 0; j < 2; ++j) {
            const int c = tid + 256 * j;
            const int r = c >> 3, c8 = (c & 7) * 8;
            const uint32_t off = (uint32_t)(r * KST2 + c8) * 2;
            cp16(kb + off, Kt + (size_t)r * kHD + c8);
            cp16(vb + off, Vt + (size_t)r * kS + c8);
        }
        cp_commit();
    };

    stage_tile(0, 0);
    stage_tile(1, 1);

    __half* Qs = reinterpret_cast<__half*>(smem + 2 * STAGE_B);
    #pragma unroll
    for (int j = 0; j < 4; ++j) {
        const int c = tid + 256 * j;
        const int r = c >> 3, c8 = (c & 7) * 8;
        uint4 v = *reinterpret_cast<const uint4*>(Qp + (size_t)r * kHD + c8);
        *reinterpret_cast<uint4*>(Qs + r * KST2 + c8) = v;
    }
    __syncthreads();

    uint32_t qa[4][4];
    {
        const int r0 = w * 16 + lr;
        #pragma unroll
        for (int ks = 0; ks < 4; ++ks) {
            const int cb = ks * 16 + 2 * lc;
            qa[ks][0] = *reinterpret_cast<const uint32_t*>(Qs + r0 * KST2 + cb);
            qa[ks][1] = *reinterpret_cast<const uint32_t*>(Qs + (r0 + 8) * KST2 + cb);
            qa[ks][2] = *reinterpret_cast<const uint32_t*>(Qs + r0 * KST2 + cb + 8);
            qa[ks][3] = *reinterpret_cast<const uint32_t*>(Qs + (r0 + 8) * KST2 + cb + 8);
        }
    }

    float oacc[8][4];
    #pragma unroll
    for (int i = 0; i < 8; ++i)
        #pragma unroll
        for (int j = 0; j < 4; ++j) oacc[i][j] = 0.f;
    float lsum0 = 0.f, lsum1 = 0.f;
    const int q0 = qt * 128 + w * 16 + lr;

    int buf = 0;
    for (int kt = 0; kt < NKT; ++kt) {
        cp_wait1();
        __syncthreads();

        const __half* Kb = reinterpret_cast<const __half*>(smem + buf * STAGE_B);
        const __half* Vb = Kb + 64 * KST2;

        #pragma unroll
        for (int sub = 0; sub < 2; ++sub) {
            float sacc[4][4];
            #pragma unroll
            for (int i = 0; i < 4; ++i)
                #pragma unroll
                for (int j = 0; j < 4; ++j) sacc[i][j] = 0.f;

            #pragma unroll
            for (int nf = 0; nf < 4; ++nf) {
                const __half* krow = Kb + (sub * 32 + nf * 8 + lr) * KST2;
                #pragma unroll
                for (int ks = 0; ks < 4; ++ks) {
                    const uint32_t b0 = *reinterpret_cast<const uint32_t*>(krow + ks * 16 + 2 * lc);
                    const uint32_t b1 = *reinterpret_cast<const uint32_t*>(krow + ks * 16 + 2 * lc + 8);
                    mma_f16(sacc[nf], qa[ks], b0, b1);
                }
            }

            uint32_t pa[2][4];
            #pragma unroll
            for (int nf = 0; nf < 4; ++nf) {
                const int colb = kt * 64 + sub * 32 + nf * 8 + 2 * lc;
                const float p0 = (colb     <= q0)     ? __expf(sacc[nf][0] * kScale) : 1.0f;
                const float p1 = (colb + 1 <= q0)     ? __expf(sacc[nf][1] * kScale) : 1.0f;
                const float p2 = (colb     <= q0 + 8) ? __expf(sacc[nf][2] * kScale) : 1.0f;
                const float p3 = (colb + 1 <= q0 + 8) ? __expf(sacc[nf][3] * kScale) : 1.0f;
                lsum0 += p0 + p1;
                lsum1 += p2 + p3;
                const int kk = nf >> 1;
                if ((nf & 1) == 0) {
                    pa[kk][0] = pack_f16(p0, p1);
                    pa[kk][1] = pack_f16(p2, p3);
                } else {
                    pa[kk][2] = pack_f16(p0, p1);
                    pa[kk][3] = pack_f16(p2, p3);
                }
            }

            #pragma unroll
            for (int nd = 0; nd < 8; ++nd) {
                const __half* vrow = Vb + (nd * 8 + lr) * KST2 + sub * 32;
                #pragma unroll
                for (int kk = 0; kk < 2; ++kk) {
                    const uint32_t b0 = *reinterpret_cast<const uint32_t*>(vrow + kk * 16 + 2 * lc);
                    const uint32_t b1 = *reinterpret_cast<const uint32_t*>(vrow + kk * 16 + 2 * lc + 8);
                    mma_f16(oacc[nd], pa[kk], b0, b1);
                }
            }
        }

        if (kt + 2 < NKT) {
            stage_tile(kt + 2, (buf + 2) % 3);
        } else {
            cp_commit();
        }
        buf = (buf + 1) % 3;
    }

    lsum0 += __shfl_xor_sync(0xffffffffu, lsum0, 1);
    lsum0 += __shfl_xor_sync(0xffffffffu, lsum0, 2);
    lsum1 += __shfl_xor_sync(0xffffffffu, lsum1, 1);
    lsum1 += __shfl_xor_sync(0xffffffffu, lsum1, 2);
    const float inv0 = 1.f / lsum0;
    const float inv1 = 1.f / lsum1;

    float* Op = g_O + (size_t)(b * kNH + h) * kHD * kS;
    #pragma unroll
    for (int nd = 0; nd < 8; ++nd) {
        const int hd = nd * 8 + 2 * lc;
        Op[(size_t)hd * kS + q0]           = oacc[nd][0] * inv0;
        Op[(size_t)(hd + 1) * kS + q0]     = oacc[nd][1] * inv0;
        Op[(size_t)hd * kS + q0 + 8]       = oacc[nd][2] * inv1;
        Op[(size_t)(hd + 1) * kS + q0 + 8] = oacc[nd][3] * inv1;
    }
}

extern "C" void kernel_launch(void* const* d_in, const int* in_sizes, int n_in,
                              void* d_out, int out_size)
{
    (void)in_sizes; (void)n_in; (void)out_size;
    const float* x  = (const float*)d_in[0];
    const float* Wq = (const float*)d_in[2];
    const float* bq = (const float*)d_in[3];
    const float* Wk = (const float*)d_in[4];
    const float* bk = (const float*)d_in[5];
    const float* Wv = (const float*)d_in[6];
    const float* bv = (const float*)d_in[7];
    const float* Wo = (const float*)d_in[8];
    const float* bo = (const float*)d_in[9];
    float* out = (float*)d_out;

    void* op;
    cudaGetSymbolAddress(&op, g_O);

    cudaFuncSetAttribute(attn_mma, cudaFuncAttributeMaxDynamicSharedMemorySize, SMEM_ATTN);
    cudaFuncSetAttribute(gemm_qkv, cudaFuncAttributeMaxDynamicSharedMemorySize, SMEM_GEMM);
    cudaFuncSetAttribute(gemm_out, cudaFuncAttributeMaxDynamicSharedMemorySize, SMEM_GEMM);

    gemm_qkv<<<dim3(1280 / 64, (kB * kS) / 128), 256, SMEM_GEMM>>>(
        x, Wq, bq, Wk, bk, Wv, bv);

    attn_mma<<<dim3(kS / 128, kNH, kB), 256, SMEM_ATTN>>>();

    gemm_out<<<dim3(kD / 64, (kB * kS) / 128), 256, SMEM_GEMM>>>(
        (const float*)op, Wo, bo, out);
}

// round 10
// speedup vs baseline: 1.6643x; 1.3380x over previous
#include <cuda_runtime.h>
#include <cuda_fp16.h>
#include <cstdint>

// GroupQuerySelfAttention: B=2, S=2048, D=768, NH=12, GH=4 (rep=3), HD=64
// MASK_FILL = -1e-9 => masked P entries == exp(-1e-9) == 1.0f; exact softmax,
// no max subtraction. Everything fp16-mma. Inputs pre-converted to f16 once
// (x and K-major-transposed weights); all GEMMs are 3-stage cp.async
// pipelines with pure-f16 smem operands. Attention writes f16 O so the
// out-projection streams it directly. Buggy merge == out stored [B,NH,HD,S].

namespace {
constexpr int kB  = 2;
constexpr int kS  = 2048;
constexpr int kD  = 768;
constexpr int kNH = 12;
constexpr int kGH = 4;
constexpr int kHD = 64;
constexpr int kREP = 3;
constexpr float kScale = 0.125f;
}

__device__ __half g_Xh [(size_t)kB * kS * kD];        // [4096, 768] f16 x
__device__ __half g_WqT[(size_t)kD * kD];             // [768][768]  W^T (n,k)
__device__ __half g_WkT[(size_t)(kGH * kHD) * kD];    // [256][768]
__device__ __half g_WvT[(size_t)(kGH * kHD) * kD];    // [256][768]
__device__ __half g_WoT[(size_t)kD * kD];             // [768][768]
__device__ __half g_Qh [(size_t)kB * kNH * kS * kHD]; // [b, h, s, hd]
__device__ __half g_Kh [(size_t)kB * kGH * kS * kHD]; // [b, g, s, hd]
__device__ __half g_Vh [(size_t)kB * kGH * kHD * kS]; // [b, g, hd, s]
__device__ __half g_Oh [(size_t)kB * kNH * kHD * kS]; // [b, h, hd, q] == [4096,768] A-matrix

// ---------------------------------------------------------------------------
// PTX helpers (baseline — compute_103-family safe)
// ---------------------------------------------------------------------------
__device__ __forceinline__ void mma_f16(float* d, const uint32_t* a,
                                        uint32_t b0, uint32_t b1) {
    asm volatile(
        "mma.sync.aligned.m16n8k16.row.col.f32.f16.f16.f32 "
        "{%0,%1,%2,%3}, {%4,%5,%6,%7}, {%8,%9}, {%0,%1,%2,%3};"
        : "+f"(d[0]), "+f"(d[1]), "+f"(d[2]), "+f"(d[3])
        : "r"(a[0]), "r"(a[1]), "r"(a[2]), "r"(a[3]), "r"(b0), "r"(b1));
}
__device__ __forceinline__ uint32_t pack_f16(float lo, float hi) {
    uint32_t r;
    asm("cvt.rn.f16x2.f32 %0, %1, %2;" : "=r"(r) : "f"(hi), "f"(lo));
    return r;
}
__device__ __forceinline__ uint32_t smem_u32(const void* p) {
    uint32_t a;
    asm("{ .reg .u64 t; cvta.to.shared.u64 t, %1; cvt.u32.u64 %0, t; }"
        : "=r"(a) : "l"(p));
    return a;
}
__device__ __forceinline__ void cp16(uint32_t dst, const void* src) {
    asm volatile("cp.async.cg.shared.global [%0], [%1], 16;"
                 :: "r"(dst), "l"(src) : "memory");
}
__device__ __forceinline__ void cp_commit() {
    asm volatile("cp.async.commit_group;" ::: "memory");
}
__device__ __forceinline__ void cp_wait1() {
    asm volatile("cp.async.wait_group 1;" ::: "memory");
}
__device__ __forceinline__ uint32_t ld32s(const __half* p) {
    return *reinterpret_cast<const uint32_t*>(p);
}

// ---------------------------------------------------------------------------
// Prep kernels: x -> f16, weights -> f16 K-major transpose
// ---------------------------------------------------------------------------
__global__ __launch_bounds__(256) void convert_x(const float* __restrict__ x)
{
    const int idx = blockIdx.x * 256 + threadIdx.x;          // 786432 float4s
    float4 v = reinterpret_cast<const float4*>(x)[idx];
    uint2 p;
    p.x = pack_f16(v.x, v.y);
    p.y = pack_f16(v.z, v.w);
    reinterpret_cast<uint2*>(g_Xh)[idx] = p;
}

__global__ __launch_bounds__(256) void convert_w(
    const float* __restrict__ Wq, const float* __restrict__ Wk,
    const float* __restrict__ Wv, const float* __restrict__ Wo)
{
    __shared__ float t[32][33];
    const int c0 = blockIdx.x * 32;     // concatenated col space [0,2048)
    const int k0 = blockIdx.y * 32;
    const float* W; __half* dst; int Nw, cl;
    if (c0 < 768)       { W = Wq; dst = g_WqT; Nw = 768; cl = c0; }
    else if (c0 < 1024) { W = Wk; dst = g_WkT; Nw = 256; cl = c0 - 768; }
    else if (c0 < 1280) { W = Wv; dst = g_WvT; Nw = 256; cl = c0 - 1024; }
    else                { W = Wo; dst = g_WoT; Nw = 768; cl = c0 - 1280; }
    const int tx = threadIdx.x & 31, ty = threadIdx.x >> 5;
    #pragma unroll
    for (int j = 0; j < 4; ++j)
        t[ty + j * 8][tx] = W[(size_t)(k0 + ty + j * 8) * Nw + cl + tx];
    __syncthreads();
    #pragma unroll
    for (int j = 0; j < 4; ++j) {
        const int n = ty + j * 8;
        dst[(size_t)(cl + n) * kD + k0 + tx] = __float2half_rn(t[tx][n]);
    }
}

// ---------------------------------------------------------------------------
// Pipelined f16 GEMM core: CTA 128m x 64n, 8 warps (16m x 64n), 32-K chunks,
// 3-stage cp.async over f16 A [m][k] and f16 W^T [n][k]. Fragments: single
// conflict-free LDS.32 (stride 40 halves).
// ---------------------------------------------------------------------------
namespace {
constexpr int GST = 40;                        // halves per smem row
constexpr int GA_B = 128 * GST * 2;            // 10240 B
constexpr int GW_B = 64 * GST * 2;             // 5120 B
constexpr int GSTAGE_B = GA_B + GW_B;          // 15360 B
constexpr int SMEM_GEMM = 3 * GSTAGE_B;        // 46080 B
constexpr int TPAD = 136;                      // V-transpose staging stride
}

__device__ __forceinline__ void gemm16_mainloop(
    uint32_t sb, const char* smem,
    const __half* __restrict__ Arow,     // base + rowBase*768
    const __half* __restrict__ Wrow,     // W^T base + colLoc*768
    int w, int lr, int lc, int tid, float (&acc)[8][4])
{
    auto stage = [&](int ch, int s) {
        const int k0 = ch * 32;
        const uint32_t ab = sb + s * GSTAGE_B;
        const uint32_t wb = ab + GA_B;
        #pragma unroll
        for (int j = 0; j < 2; ++j) {
            const int idx = tid + 256 * j;
            const int r = idx >> 2, c4 = idx & 3;
            cp16(ab + (uint32_t)(r * GST + c4 * 8) * 2,
                 Arow + (size_t)r * kD + k0 + c4 * 8);
        }
        {
            const int r = tid >> 2, c4 = tid & 3;
            cp16(wb + (uint32_t)(r * GST + c4 * 8) * 2,
                 Wrow + (size_t)r * kD + k0 + c4 * 8);
        }
        cp_commit();
    };

    stage(0, 0);
    stage(1, 1);

    const int r0 = w * 16 + lr;
    const int nch = kD / 32;   // 24
    int buf = 0;
    for (int ch = 0; ch < nch; ++ch) {
        cp_wait1();
        __syncthreads();
        const __half* Ab = reinterpret_cast<const __half*>(smem + buf * GSTAGE_B);
        const __half* Wb = Ab + 128 * GST;
        #pragma unroll
        for (int ks = 0; ks < 2; ++ks) {
            const int cb = ks * 16 + 2 * lc;
            uint32_t a[4];
            a[0] = ld32s(Ab + r0 * GST + cb);
            a[1] = ld32s(Ab + (r0 + 8) * GST + cb);
            a[2] = ld32s(Ab + r0 * GST + cb + 8);
            a[3] = ld32s(Ab + (r0 + 8) * GST + cb + 8);
            #pragma unroll
            for (int nf = 0; nf < 8; ++nf) {
                const __half* wrow = Wb + (nf * 8 + lr) * GST;
                mma_f16(acc[nf], a, ld32s(wrow + cb), ld32s(wrow + cb + 8));
            }
        }
        if (ch + 2 < nch) stage(ch + 2, (buf + 2) % 3);
        else cp_commit();
        buf = (buf + 1) % 3;
    }
}

// Merged QKV projection: columns 0..767 Q, 768..1023 K, 1024..1279 V (V
// epilogue transposes to [b,g,hd,s] via smem for coalesced 16B stores).
__global__ __launch_bounds__(256) void gemm_qkv(
    const float* __restrict__ bq, const float* __restrict__ bk,
    const float* __restrict__ bv)
{
    extern __shared__ char smem[];
    const uint32_t sb = smem_u32(smem);
    const int tid = threadIdx.x;
    const int lane = tid & 31;
    const int w = tid >> 5;
    const int lr = lane >> 2, lc = lane & 3;
    const int rowBase = blockIdx.y * 128;
    const int colBase = blockIdx.x * 64;

    const __half* WT; const float* bias; int colLoc, seg;
    if (colBase < 768)       { WT = g_WqT; bias = bq; colLoc = colBase;        seg = 0; }
    else if (colBase < 1024) { WT = g_WkT; bias = bk; colLoc = colBase - 768;  seg = 1; }
    else                     { WT = g_WvT; bias = bv; colLoc = colBase - 1024; seg = 2; }

    float acc[8][4];
    #pragma unroll
    for (int i = 0; i < 8; ++i)
        #pragma unroll
        for (int j = 0; j < 4; ++j) acc[i][j] = 0.f;

    gemm16_mainloop(sb, smem, g_Xh + (size_t)rowBase * kD,
                    WT + (size_t)colLoc * kD, w, lr, lc, tid, acc);

    const int bb = rowBase / kS;
    const int s0 = rowBase - bb * kS;

    if (seg == 2) {
        __syncthreads();                       // smem reuse after mainloop
        __half* T = reinterpret_cast<__half*>(smem);   // [64][TPAD]
        #pragma unroll
        for (int half = 0; half < 2; ++half) {
            const int r = w * 16 + lr + half * 8;
            #pragma unroll
            for (int nf = 0; nf < 8; ++nf) {
                const int c = nf * 8 + 2 * lc;
                T[(c + 0) * TPAD + r] = __float2half_rn(acc[nf][half * 2 + 0] + bias[colLoc + c]);
                T[(c + 1) * TPAD + r] = __float2half_rn(acc[nf][half * 2 + 1] + bias[colLoc + c + 1]);
            }
        }
        __syncthreads();
        const int g = colLoc / kHD;
        __half* base = g_Vh + (size_t)(bb * kGH + g) * kHD * kS;
        #pragma unroll
        for (int j = 0; j < 4; ++j) {
            const int idx = tid + 256 * j;
            const int hd = idx >> 4, ch8 = (idx & 15) * 8;
            uint4 v = *reinterpret_cast<const uint4*>(T + hd * TPAD + ch8);
            *reinterpret_cast<uint4*>(base + (size_t)hd * kS + s0 + ch8) = v;
        }
    } else {
        __half* out = (seg == 0) ? g_Qh : g_Kh;
        const int heads = (seg == 0) ? kNH : kGH;
        #pragma unroll
        for (int half = 0; half < 2; ++half) {
            const int s = s0 + w * 16 + lr + half * 8;
            #pragma unroll
            for (int nf = 0; nf < 8; ++nf) {
                const int c = colLoc + nf * 8 + 2 * lc;
                const int h = c / kHD, cc = c - h * kHD;
                const float v0 = acc[nf][half * 2 + 0] + bias[c];
                const float v1 = acc[nf][half * 2 + 1] + bias[c + 1];
                __half* dst = out + ((size_t)(bb * heads + h) * kS + s) * kHD + cc;
                *reinterpret_cast<uint32_t*>(dst) = pack_f16(v0, v1);
            }
        }
    }
}

// Out-projection: d_out[4096 x 768] = g_Oh @ Wo + bo (f32 output)
__global__ __launch_bounds__(256) void gemm_out(
    const float* __restrict__ bias, float* __restrict__ out)
{
    extern __shared__ char smem[];
    const uint32_t sb = smem_u32(smem);
    const int tid = threadIdx.x;
    const int lane = tid & 31;
    const int w = tid >> 5;
    const int lr = lane >> 2, lc = lane & 3;
    const int rowBase = blockIdx.y * 128;
    const int colBase = blockIdx.x * 64;

    float acc[8][4];
    #pragma unroll
    for (int i = 0; i < 8; ++i)
        #pragma unroll
        for (int j = 0; j < 4; ++j) acc[i][j] = 0.f;

    gemm16_mainloop(sb, smem, g_Oh + (size_t)rowBase * kD,
                    g_WoT + (size_t)colBase * kD, w, lr, lc, tid, acc);

    #pragma unroll
    for (int half = 0; half < 2; ++half) {
        const int r = rowBase + w * 16 + lr + half * 8;
        #pragma unroll
        for (int nf = 0; nf < 8; ++nf) {
            const int c = colBase + nf * 8 + 2 * lc;
            float* dst = out + (size_t)r * kD + c;
            dst[0] = acc[nf][half * 2 + 0] + bias[c];
            dst[1] = acc[nf][half * 2 + 1] + bias[c + 1];
        }
    }
}

// ---------------------------------------------------------------------------
// Pipelined all-fp16 attention (proven 103 us) — epilogue now writes f16 g_Oh
// ---------------------------------------------------------------------------
namespace {
constexpr int KST2 = 72;
constexpr int TILE_B = 64 * KST2 * 2;
constexpr int STAGE_B = 2 * TILE_B;
constexpr int SMEM_ATTN = 3 * STAGE_B;         // 55296 B
constexpr int NKT = kS / 64;
}

__global__ __launch_bounds__(256, 2) void attn_mma()
{
    extern __shared__ char smem[];
    const uint32_t sb = smem_u32(smem);

    const int tid = threadIdx.x;
    const int lane = tid & 31;
    const int w = tid >> 5;
    const int qt = blockIdx.x, h = blockIdx.y, b = blockIdx.z;
    const int g = h / kREP;
    const int lr = lane >> 2, lc = lane & 3;

    const __half* Qp = g_Qh + ((size_t)(b * kNH + h) * kS + (size_t)qt * 128) * kHD;
    const __half* Kp = g_Kh + (size_t)(b * kGH + g) * kS * kHD;
    const __half* Vp = g_Vh + (size_t)(b * kGH + g) * kHD * kS;

    auto stage_tile = [&](int kt, int s) {
        const __half* Kt = Kp + (size_t)kt * 64 * kHD;
        const __half* Vt = Vp + (size_t)kt * 64;
        const uint32_t kb = sb + s * STAGE_B;
        const uint32_t vb = kb + TILE_B;
        #pragma unroll
        for (int j = 0; j < 2; ++j) {
            const int c = tid + 256 * j;
            const int r = c >> 3, c8 = (c & 7) * 8;
            const uint32_t off = (uint32_t)(r * KST2 + c8) * 2;
            cp16(kb + off, Kt + (size_t)r * kHD + c8);
            cp16(vb + off, Vt + (size_t)r * kS + c8);
        }
        cp_commit();
    };

    stage_tile(0, 0);
    stage_tile(1, 1);

    __half* Qs = reinterpret_cast<__half*>(smem + 2 * STAGE_B);
    #pragma unroll
    for (int j = 0; j < 4; ++j) {
        const int c = tid + 256 * j;
        const int r = c >> 3, c8 = (c & 7) * 8;
        uint4 v = *reinterpret_cast<const uint4*>(Qp + (size_t)r * kHD + c8);
        *reinterpret_cast<uint4*>(Qs + r * KST2 + c8) = v;
    }
    __syncthreads();

    uint32_t qa[4][4];
    {
        const int r0 = w * 16 + lr;
        #pragma unroll
        for (int ks = 0; ks < 4; ++ks) {
            const int cb = ks * 16 + 2 * lc;
            qa[ks][0] = ld32s(Qs + r0 * KST2 + cb);
            qa[ks][1] = ld32s(Qs + (r0 + 8) * KST2 + cb);
            qa[ks][2] = ld32s(Qs + r0 * KST2 + cb + 8);
            qa[ks][3] = ld32s(Qs + (r0 + 8) * KST2 + cb + 8);
        }
    }

    float oacc[8][4];
    #pragma unroll
    for (int i = 0; i < 8; ++i)
        #pragma unroll
        for (int j = 0; j < 4; ++j) oacc[i][j] = 0.f;
    float lsum0 = 0.f, lsum1 = 0.f;
    const int q0 = qt * 128 + w * 16 + lr;

    int buf = 0;
    for (int kt = 0; kt < NKT; ++kt) {
        cp_wait1();
        __syncthreads();

        const __half* Kb = reinterpret_cast<const __half*>(smem + buf * STAGE_B);
        const __half* Vb = Kb + 64 * KST2;

        #pragma unroll
        for (int sub = 0; sub < 2; ++sub) {
            float sacc[4][4];
            #pragma unroll
            for (int i = 0; i < 4; ++i)
                #pragma unroll
                for (int j = 0; j < 4; ++j) sacc[i][j] = 0.f;

            #pragma unroll
            for (int nf = 0; nf < 4; ++nf) {
                const __half* krow = Kb + (sub * 32 + nf * 8 + lr) * KST2;
                #pragma unroll
                for (int ks = 0; ks < 4; ++ks) {
                    mma_f16(sacc[nf], qa[ks],
                            ld32s(krow + ks * 16 + 2 * lc),
                            ld32s(krow + ks * 16 + 2 * lc + 8));
                }
            }

            uint32_t pa[2][4];
            #pragma unroll
            for (int nf = 0; nf < 4; ++nf) {
                const int colb = kt * 64 + sub * 32 + nf * 8 + 2 * lc;
                const float p0 = (colb     <= q0)     ? __expf(sacc[nf][0] * kScale) : 1.0f;
                const float p1 = (colb + 1 <= q0)     ? __expf(sacc[nf][1] * kScale) : 1.0f;
                const float p2 = (colb     <= q0 + 8) ? __expf(sacc[nf][2] * kScale) : 1.0f;
                const float p3 = (colb + 1 <= q0 + 8) ? __expf(sacc[nf][3] * kScale) : 1.0f;
                lsum0 += p0 + p1;
                lsum1 += p2 + p3;
                const int kk = nf >> 1;
                if ((nf & 1) == 0) {
                    pa[kk][0] = pack_f16(p0, p1);
                    pa[kk][1] = pack_f16(p2, p3);
                } else {
                    pa[kk][2] = pack_f16(p0, p1);
                    pa[kk][3] = pack_f16(p2, p3);
                }
            }

            #pragma unroll
            for (int nd = 0; nd < 8; ++nd) {
                const __half* vrow = Vb + (nd * 8 + lr) * KST2 + sub * 32;
                #pragma unroll
                for (int kk = 0; kk < 2; ++kk) {
                    mma_f16(oacc[nd], pa[kk],
                            ld32s(vrow + kk * 16 + 2 * lc),
                            ld32s(vrow + kk * 16 + 2 * lc + 8));
                }
            }
        }

        if (kt + 2 < NKT) stage_tile(kt + 2, (buf + 2) % 3);
        else cp_commit();
        buf = (buf + 1) % 3;
    }

    lsum0 += __shfl_xor_sync(0xffffffffu, lsum0, 1);
    lsum0 += __shfl_xor_sync(0xffffffffu, lsum0, 2);
    lsum1 += __shfl_xor_sync(0xffffffffu, lsum1, 1);
    lsum1 += __shfl_xor_sync(0xffffffffu, lsum1, 2);
    const float inv0 = 1.f / lsum0;
    const float inv1 = 1.f / lsum1;

    __half* Op = g_Oh + (size_t)(b * kNH + h) * kHD * kS;
    #pragma unroll
    for (int nd = 0; nd < 8; ++nd) {
        const int hd = nd * 8 + 2 * lc;
        Op[(size_t)hd * kS + q0]           = __float2half_rn(oacc[nd][0] * inv0);
        Op[(size_t)(hd + 1) * kS + q0]     = __float2half_rn(oacc[nd][1] * inv0);
        Op[(size_t)hd * kS + q0 + 8]       = __float2half_rn(oacc[nd][2] * inv1);
        Op[(size_t)(hd + 1) * kS + q0 + 8] = __float2half_rn(oacc[nd][3] * inv1);
    }
}

extern "C" void kernel_launch(void* const* d_in, const int* in_sizes, int n_in,
                              void* d_out, int out_size)
{
    (void)in_sizes; (void)n_in; (void)out_size;
    const float* x  = (const float*)d_in[0];
    const float* Wq = (const float*)d_in[2];
    const float* bq = (const float*)d_in[3];
    const float* Wk = (const float*)d_in[4];
    const float* bk = (const float*)d_in[5];
    const float* Wv = (const float*)d_in[6];
    const float* bv = (const float*)d_in[7];
    const float* Wo = (const float*)d_in[8];
    const float* bo = (const float*)d_in[9];
    float* out = (float*)d_out;

    cudaFuncSetAttribute(attn_mma, cudaFuncAttributeMaxDynamicSharedMemorySize, SMEM_ATTN);
    cudaFuncSetAttribute(gemm_qkv, cudaFuncAttributeMaxDynamicSharedMemorySize, SMEM_GEMM);
    cudaFuncSetAttribute(gemm_out, cudaFuncAttributeMaxDynamicSharedMemorySize, SMEM_GEMM);

    convert_x<<<(kB * kS * kD / 4) / 256, 256>>>(x);
    convert_w<<<dim3(2048 / 32, kD / 32), 256>>>(Wq, Wk, Wv, Wo);

    gemm_qkv<<<dim3(1280 / 64, (kB * kS) / 128), 256, SMEM_GEMM>>>(bq, bk, bv);

    attn_mma<<<dim3(kS / 128, kNH, kB), 256, SMEM_ATTN>>>();

    gemm_out<<<dim3(kD / 64, (kB * kS) / 128), 256, SMEM_GEMM>>>(bo, out);
}

// round 12
// speedup vs baseline: 1.7117x; 1.0285x over previous
#include <cuda_runtime.h>
#include <cuda_fp16.h>
#include <cstdint>

// GroupQuerySelfAttention: B=2, S=2048, D=768, NH=12, GH=4 (rep=3), HD=64
// MASK_FILL = -1e-9 => masked p == exp(-1e-9) == 1.0f exactly. Fully-masked
// (future) key tiles contribute colsum(V-tile) to O (query-independent) and
// +count to lsum => precompute V suffix sums, skip ~half the attention tiles.
// R12 fix: masked-tail lsum added AFTER the quad-lane reduction (was 4x).
// All GEMMs fp16-mma cp.async pipelines. Buggy merge == out as [B,NH,HD,S].

namespace {
constexpr int kB  = 2;
constexpr int kS  = 2048;
constexpr int kD  = 768;
constexpr int kNH = 12;
constexpr int kGH = 4;
constexpr int kHD = 64;
constexpr int kREP = 3;
constexpr float kScale = 0.125f;
}

__device__ __half g_Xh [(size_t)kB * kS * kD];
__device__ __half g_WqT[(size_t)kD * kD];
__device__ __half g_WkT[(size_t)(kGH * kHD) * kD];
__device__ __half g_WvT[(size_t)(kGH * kHD) * kD];
__device__ __half g_WoT[(size_t)kD * kD];
__device__ __half g_Qh [(size_t)kB * kNH * kS * kHD];
__device__ __half g_Kh [(size_t)kB * kGH * kS * kHD];
__device__ __half g_Vh [(size_t)kB * kGH * kHD * kS];  // [b, g, hd, s]
__device__ __half g_Oh [(size_t)kB * kNH * kHD * kS];  // [b, h, hd, q]
__device__ float  g_Vsuf[(size_t)kB * kGH * 33 * kHD]; // suffix V tile colsums

// ---------------------------------------------------------------------------
__device__ __forceinline__ void mma_f16(float* d, const uint32_t* a,
                                        uint32_t b0, uint32_t b1) {
    asm volatile(
        "mma.sync.aligned.m16n8k16.row.col.f32.f16.f16.f32 "
        "{%0,%1,%2,%3}, {%4,%5,%6,%7}, {%8,%9}, {%0,%1,%2,%3};"
        : "+f"(d[0]), "+f"(d[1]), "+f"(d[2]), "+f"(d[3])
        : "r"(a[0]), "r"(a[1]), "r"(a[2]), "r"(a[3]), "r"(b0), "r"(b1));
}
__device__ __forceinline__ uint32_t pack_f16(float lo, float hi) {
    uint32_t r;
    asm("cvt.rn.f16x2.f32 %0, %1, %2;" : "=r"(r) : "f"(hi), "f"(lo));
    return r;
}
__device__ __forceinline__ uint32_t smem_u32(const void* p) {
    uint32_t a;
    asm("{ .reg .u64 t; cvta.to.shared.u64 t, %1; cvt.u32.u64 %0, t; }"
        : "=r"(a) : "l"(p));
    return a;
}
__device__ __forceinline__ void cp16(uint32_t dst, const void* src) {
    asm volatile("cp.async.cg.shared.global [%0], [%1], 16;"
                 :: "r"(dst), "l"(src) : "memory");
}
__device__ __forceinline__ void cp_commit() {
    asm volatile("cp.async.commit_group;" ::: "memory");
}
__device__ __forceinline__ void cp_wait1() {
    asm volatile("cp.async.wait_group 1;" ::: "memory");
}
__device__ __forceinline__ uint32_t ld32s(const __half* p) {
    return *reinterpret_cast<const uint32_t*>(p);
}

// ---------------------------------------------------------------------------
// Prep kernels
// ---------------------------------------------------------------------------
__global__ __launch_bounds__(256) void convert_x(const float* __restrict__ x)
{
    const int idx = blockIdx.x * 256 + threadIdx.x;
    float4 v = reinterpret_cast<const float4*>(x)[idx];
    uint2 p;
    p.x = pack_f16(v.x, v.y);
    p.y = pack_f16(v.z, v.w);
    reinterpret_cast<uint2*>(g_Xh)[idx] = p;
}

__global__ __launch_bounds__(256) void convert_w(
    const float* __restrict__ Wq, const float* __restrict__ Wk,
    const float* __restrict__ Wv, const float* __restrict__ Wo)
{
    __shared__ float t[32][33];
    const int c0 = blockIdx.x * 32;
    const int k0 = blockIdx.y * 32;
    const float* W; __half* dst; int Nw, cl;
    if (c0 < 768)       { W = Wq; dst = g_WqT; Nw = 768; cl = c0; }
    else if (c0 < 1024) { W = Wk; dst = g_WkT; Nw = 256; cl = c0 - 768; }
    else if (c0 < 1280) { W = Wv; dst = g_WvT; Nw = 256; cl = c0 - 1024; }
    else                { W = Wo; dst = g_WoT; Nw = 768; cl = c0 - 1280; }
    const int tx = threadIdx.x & 31, ty = threadIdx.x >> 5;
    #pragma unroll
    for (int j = 0; j < 4; ++j)
        t[ty + j * 8][tx] = W[(size_t)(k0 + ty + j * 8) * Nw + cl + tx];
    __syncthreads();
    #pragma unroll
    for (int j = 0; j < 4; ++j) {
        const int n = ty + j * 8;
        dst[(size_t)(cl + n) * kD + k0 + tx] = __float2half_rn(t[tx][n]);
    }
}

// V suffix tile-colsum: g_Vsuf[b][g][jt][hd] = sum_{k >= jt*64} V[b,g,k,hd]
__global__ __launch_bounds__(256) void vsuf_kernel()
{
    __shared__ float ts[64][33];
    const int bg = blockIdx.x;
    const int w = threadIdx.x >> 5, lane = threadIdx.x & 31;
    const __half* Vb = g_Vh + (size_t)bg * kHD * kS;

    for (int hd = w; hd < kHD; hd += 8) {
        const __half* row = Vb + (size_t)hd * kS;
        for (int t = 0; t < 32; ++t) {
            const uint32_t pk = ld32s(row + t * 64 + lane * 2);
            const __half2 h2 = *reinterpret_cast<const __half2*>(&pk);
            float s = __half2float(h2.x) + __half2float(h2.y);
            #pragma unroll
            for (int off = 16; off >= 1; off >>= 1)
                s += __shfl_xor_sync(0xffffffffu, s, off);
            if (lane == 0) ts[hd][t] = s;
        }
    }
    __syncthreads();
    if (threadIdx.x < 64) {
        const int hd = threadIdx.x;
        float acc = 0.f;
        float* dst = g_Vsuf + (size_t)bg * 33 * kHD;
        dst[32 * kHD + hd] = 0.f;
        for (int jt = 31; jt >= 0; --jt) {
            acc += ts[hd][jt];
            dst[jt * kHD + hd] = acc;
        }
    }
}

// ---------------------------------------------------------------------------
// Pipelined f16 GEMM core (proven R10)
// ---------------------------------------------------------------------------
namespace {
constexpr int GST = 40;
constexpr int GA_B = 128 * GST * 2;
constexpr int GW_B = 64 * GST * 2;
constexpr int GSTAGE_B = GA_B + GW_B;          // 15360 B
constexpr int SMEM_GEMM = 3 * GSTAGE_B;        // 46080 B
constexpr int TPAD = 136;
}

__device__ __forceinline__ void gemm16_mainloop(
    uint32_t sb, const char* smem,
    const __half* __restrict__ Arow, const __half* __restrict__ Wrow,
    int w, int lr, int lc, int tid, float (&acc)[8][4])
{
    auto stage = [&](int ch, int s) {
        const int k0 = ch * 32;
        const uint32_t ab = sb + s * GSTAGE_B;
        const uint32_t wb = ab + GA_B;
        #pragma unroll
        for (int j = 0; j < 2; ++j) {
            const int idx = tid + 256 * j;
            const int r = idx >> 2, c4 = idx & 3;
            cp16(ab + (uint32_t)(r * GST + c4 * 8) * 2,
                 Arow + (size_t)r * kD + k0 + c4 * 8);
        }
        {
            const int r = tid >> 2, c4 = tid & 3;
            cp16(wb + (uint32_t)(r * GST + c4 * 8) * 2,
                 Wrow + (size_t)r * kD + k0 + c4 * 8);
        }
        cp_commit();
    };

    stage(0, 0);
    stage(1, 1);

    const int r0 = w * 16 + lr;
    const int nch = kD / 32;
    int buf = 0;
    for (int ch = 0; ch < nch; ++ch) {
        cp_wait1();
        __syncthreads();
        const __half* Ab = reinterpret_cast<const __half*>(smem + buf * GSTAGE_B);
        const __half* Wb = Ab + 128 * GST;
        #pragma unroll
        for (int ks = 0; ks < 2; ++ks) {
            const int cb = ks * 16 + 2 * lc;
            uint32_t a[4];
            a[0] = ld32s(Ab + r0 * GST + cb);
            a[1] = ld32s(Ab + (r0 + 8) * GST + cb);
            a[2] = ld32s(Ab + r0 * GST + cb + 8);
            a[3] = ld32s(Ab + (r0 + 8) * GST + cb + 8);
            #pragma unroll
            for (int nf = 0; nf < 8; ++nf) {
                const __half* wrow = Wb + (nf * 8 + lr) * GST;
                mma_f16(acc[nf], a, ld32s(wrow + cb), ld32s(wrow + cb + 8));
            }
        }
        if (ch + 2 < nch) stage(ch + 2, (buf + 2) % 3);
        else cp_commit();
        buf = (buf + 1) % 3;
    }
}

__global__ __launch_bounds__(256) void gemm_qkv(
    const float* __restrict__ bq, const float* __restrict__ bk,
    const float* __restrict__ bv)
{
    extern __shared__ char smem[];
    const uint32_t sb = smem_u32(smem);
    const int tid = threadIdx.x;
    const int lane = tid & 31;
    const int w = tid >> 5;
    const int lr = lane >> 2, lc = lane & 3;
    const int rowBase = blockIdx.y * 128;
    const int colBase = blockIdx.x * 64;

    const __half* WT; const float* bias; int colLoc, seg;
    if (colBase < 768)       { WT = g_WqT; bias = bq; colLoc = colBase;        seg = 0; }
    else if (colBase < 1024) { WT = g_WkT; bias = bk; colLoc = colBase - 768;  seg = 1; }
    else                     { WT = g_WvT; bias = bv; colLoc = colBase - 1024; seg = 2; }

    float acc[8][4];
    #pragma unroll
    for (int i = 0; i < 8; ++i)
        #pragma unroll
        for (int j = 0; j < 4; ++j) acc[i][j] = 0.f;

    gemm16_mainloop(sb, smem, g_Xh + (size_t)rowBase * kD,
                    WT + (size_t)colLoc * kD, w, lr, lc, tid, acc);

    const int bb = rowBase / kS;
    const int s0 = rowBase - bb * kS;

    if (seg == 2) {
        __syncthreads();
        __half* T = reinterpret_cast<__half*>(smem);   // [64][TPAD]
        #pragma unroll
        for (int half = 0; half < 2; ++half) {
            const int r = w * 16 + lr + half * 8;
            #pragma unroll
            for (int nf = 0; nf < 8; ++nf) {
                const int c = nf * 8 + 2 * lc;
                T[(c + 0) * TPAD + r] = __float2half_rn(acc[nf][half * 2 + 0] + bias[colLoc + c]);
                T[(c + 1) * TPAD + r] = __float2half_rn(acc[nf][half * 2 + 1] + bias[colLoc + c + 1]);
            }
        }
        __syncthreads();
        const int g = colLoc / kHD;
        __half* base = g_Vh + (size_t)(bb * kGH + g) * kHD * kS;
        #pragma unroll
        for (int j = 0; j < 4; ++j) {
            const int idx = tid + 256 * j;
            const int hd = idx >> 4, ch8 = (idx & 15) * 8;
            uint4 v = *reinterpret_cast<const uint4*>(T + hd * TPAD + ch8);
            *reinterpret_cast<uint4*>(base + (size_t)hd * kS + s0 + ch8) = v;
        }
    } else {
        __half* out = (seg == 0) ? g_Qh : g_Kh;
        const int heads = (seg == 0) ? kNH : kGH;
        #pragma unroll
        for (int half = 0; half < 2; ++half) {
            const int s = s0 + w * 16 + lr + half * 8;
            #pragma unroll
            for (int nf = 0; nf < 8; ++nf) {
                const int c = colLoc + nf * 8 + 2 * lc;
                const int h = c / kHD, cc = c - h * kHD;
                const float v0 = acc[nf][half * 2 + 0] + bias[c];
                const float v1 = acc[nf][half * 2 + 1] + bias[c + 1];
                __half* dst = out + ((size_t)(bb * heads + h) * kS + s) * kHD + cc;
                *reinterpret_cast<uint32_t*>(dst) = pack_f16(v0, v1);
            }
        }
    }
}

__global__ __launch_bounds__(256) void gemm_out(
    const float* __restrict__ bias, float* __restrict__ out)
{
    extern __shared__ char smem[];
    const uint32_t sb = smem_u32(smem);
    const int tid = threadIdx.x;
    const int lane = tid & 31;
    const int w = tid >> 5;
    const int lr = lane >> 2, lc = lane & 3;
    const int rowBase = blockIdx.y * 128;
    const int colBase = blockIdx.x * 64;

    float acc[8][4];
    #pragma unroll
    for (int i = 0; i < 8; ++i)
        #pragma unroll
        for (int j = 0; j < 4; ++j) acc[i][j] = 0.f;

    gemm16_mainloop(sb, smem, g_Oh + (size_t)rowBase * kD,
                    g_WoT + (size_t)colBase * kD, w, lr, lc, tid, acc);

    #pragma unroll
    for (int half = 0; half < 2; ++half) {
        const int r = rowBase + w * 16 + lr + half * 8;
        #pragma unroll
        for (int nf = 0; nf < 8; ++nf) {
            const int c = colBase + nf * 8 + 2 * lc;
            float* dst = out + (size_t)r * kD + c;
            dst[0] = acc[nf][half * 2 + 0] + bias[c];
            dst[1] = acc[nf][half * 2 + 1] + bias[c + 1];
        }
    }
}

// ---------------------------------------------------------------------------
// Attention with masked-tail skipping (kt < ktmax = 2*qt+2), suffix via Vsuf.
// qt reversed so longest CTAs launch first.
// ---------------------------------------------------------------------------
namespace {
constexpr int KST2 = 72;
constexpr int TILE_B = 64 * KST2 * 2;
constexpr int STAGE_B = 2 * TILE_B;
constexpr int SMEM_ATTN = 3 * STAGE_B;         // 55296 B
}

__global__ __launch_bounds__(256, 2) void attn_mma()
{
    extern __shared__ char smem[];
    const uint32_t sb = smem_u32(smem);

    const int tid = threadIdx.x;
    const int lane = tid & 31;
    const int w = tid >> 5;
    const int qt = (int)gridDim.x - 1 - (int)blockIdx.x;   // long CTAs first
    const int h = blockIdx.y, b = blockIdx.z;
    const int g = h / kREP;
    const int lr = lane >> 2, lc = lane & 3;
    const int ktmax = 2 * qt + 2;

    const __half* Qp = g_Qh + ((size_t)(b * kNH + h) * kS + (size_t)qt * 128) * kHD;
    const __half* Kp = g_Kh + (size_t)(b * kGH + g) * kS * kHD;
    const __half* Vp = g_Vh + (size_t)(b * kGH + g) * kHD * kS;

    auto stage_tile = [&](int kt, int s) {
        const __half* Kt = Kp + (size_t)kt * 64 * kHD;
        const __half* Vt = Vp + (size_t)kt * 64;
        const uint32_t kb = sb + s * STAGE_B;
        const uint32_t vb = kb + TILE_B;
        #pragma unroll
        for (int j = 0; j < 2; ++j) {
            const int c = tid + 256 * j;
            const int r = c >> 3, c8 = (c & 7) * 8;
            const uint32_t off = (uint32_t)(r * KST2 + c8) * 2;
            cp16(kb + off, Kt + (size_t)r * kHD + c8);
            cp16(vb + off, Vt + (size_t)r * kS + c8);
        }
        cp_commit();
    };

    stage_tile(0, 0);
    stage_tile(1, 1);

    __half* Qs = reinterpret_cast<__half*>(smem + 2 * STAGE_B);
    #pragma unroll
    for (int j = 0; j < 4; ++j) {
        const int c = tid + 256 * j;
        const int r = c >> 3, c8 = (c & 7) * 8;
        uint4 v = *reinterpret_cast<const uint4*>(Qp + (size_t)r * kHD + c8);
        *reinterpret_cast<uint4*>(Qs + r * KST2 + c8) = v;
    }
    __syncthreads();

    uint32_t qa[4][4];
    {
        const int r0 = w * 16 + lr;
        #pragma unroll
        for (int ks = 0; ks < 4; ++ks) {
            const int cb = ks * 16 + 2 * lc;
            qa[ks][0] = ld32s(Qs + r0 * KST2 + cb);
            qa[ks][1] = ld32s(Qs + (r0 + 8) * KST2 + cb);
            qa[ks][2] = ld32s(Qs + r0 * KST2 + cb + 8);
            qa[ks][3] = ld32s(Qs + (r0 + 8) * KST2 + cb + 8);
        }
    }

    float oacc[8][4];
    #pragma unroll
    for (int i = 0; i < 8; ++i)
        #pragma unroll
        for (int j = 0; j < 4; ++j) oacc[i][j] = 0.f;
    float lsum0 = 0.f, lsum1 = 0.f;
    const int q0 = qt * 128 + w * 16 + lr;

    int buf = 0;
    for (int kt = 0; kt < ktmax; ++kt) {
        cp_wait1();
        __syncthreads();

        const __half* Kb = reinterpret_cast<const __half*>(smem + buf * STAGE_B);
        const __half* Vb = Kb + 64 * KST2;

        #pragma unroll
        for (int sub = 0; sub < 2; ++sub) {
            float sacc[4][4];
            #pragma unroll
            for (int i = 0; i < 4; ++i)
                #pragma unroll
                for (int j = 0; j < 4; ++j) sacc[i][j] = 0.f;

            #pragma unroll
            for (int nf = 0; nf < 4; ++nf) {
                const __half* krow = Kb + (sub * 32 + nf * 8 + lr) * KST2;
                #pragma unroll
                for (int ks = 0; ks < 4; ++ks) {
                    mma_f16(sacc[nf], qa[ks],
                            ld32s(krow + ks * 16 + 2 * lc),
                            ld32s(krow + ks * 16 + 2 * lc + 8));
                }
            }

            uint32_t pa[2][4];
            #pragma unroll
            for (int nf = 0; nf < 4; ++nf) {
                const int colb = kt * 64 + sub * 32 + nf * 8 + 2 * lc;
                const float p0 = (colb     <= q0)     ? __expf(sacc[nf][0] * kScale) : 1.0f;
                const float p1 = (colb + 1 <= q0)     ? __expf(sacc[nf][1] * kScale) : 1.0f;
                const float p2 = (colb     <= q0 + 8) ? __expf(sacc[nf][2] * kScale) : 1.0f;
                const float p3 = (colb + 1 <= q0 + 8) ? __expf(sacc[nf][3] * kScale) : 1.0f;
                lsum0 += p0 + p1;
                lsum1 += p2 + p3;
                const int kk = nf >> 1;
                if ((nf & 1) == 0) {
                    pa[kk][0] = pack_f16(p0, p1);
                    pa[kk][1] = pack_f16(p2, p3);
                } else {
                    pa[kk][2] = pack_f16(p0, p1);
                    pa[kk][3] = pack_f16(p2, p3);
                }
            }

            #pragma unroll
            for (int nd = 0; nd < 8; ++nd) {
                const __half* vrow = Vb + (nd * 8 + lr) * KST2 + sub * 32;
                #pragma unroll
                for (int kk = 0; kk < 2; ++kk) {
                    mma_f16(oacc[nd], pa[kk],
                            ld32s(vrow + kk * 16 + 2 * lc),
                            ld32s(vrow + kk * 16 + 2 * lc + 8));
                }
            }
        }

        if (kt + 2 < ktmax) stage_tile(kt + 2, (buf + 2) % 3);
        else cp_commit();
        buf = (buf + 1) % 3;
    }

    // fully-masked suffix: O += colsum(V[ktmax*64:]) (per-lane elements are
    // unique (row,hd) -> direct add is correct)
    const float* suf = g_Vsuf + ((size_t)(b * kGH + g) * 33 + ktmax) * kHD;
    #pragma unroll
    for (int nd = 0; nd < 8; ++nd) {
        const int hd = nd * 8 + 2 * lc;
        const float s0v = suf[hd], s1v = suf[hd + 1];
        oacc[nd][0] += s0v; oacc[nd][1] += s1v;
        oacc[nd][2] += s0v; oacc[nd][3] += s1v;
    }

    // quad-reduce the processed-range row sums, THEN add tail once (R11 bug:
    // adding before the shfl counted the tail 4x)
    lsum0 += __shfl_xor_sync(0xffffffffu, lsum0, 1);
    lsum0 += __shfl_xor_sync(0xffffffffu, lsum0, 2);
    lsum1 += __shfl_xor_sync(0xffffffffu, lsum1, 1);
    lsum1 += __shfl_xor_sync(0xffffffffu, lsum1, 2);
    const float tail = (float)(kS - ktmax * 64);
    const float inv0 = 1.f / (lsum0 + tail);
    const float inv1 = 1.f / (lsum1 + tail);

    __half* Op = g_Oh + (size_t)(b * kNH + h) * kHD * kS;
    #pragma unroll
    for (int nd = 0; nd < 8; ++nd) {
        const int hd = nd * 8 + 2 * lc;
        Op[(size_t)hd * kS + q0]           = __float2half_rn(oacc[nd][0] * inv0);
        Op[(size_t)(hd + 1) * kS + q0]     = __float2half_rn(oacc[nd][1] * inv0);
        Op[(size_t)hd * kS + q0 + 8]       = __float2half_rn(oacc[nd][2] * inv1);
        Op[(size_t)(hd + 1) * kS + q0 + 8] = __float2half_rn(oacc[nd][3] * inv1);
    }
}

extern "C" void kernel_launch(void* const* d_in, const int* in_sizes, int n_in,
                              void* d_out, int out_size)
{
    (void)in_sizes; (void)n_in; (void)out_size;
    const float* x  = (const float*)d_in[0];
    const float* Wq = (const float*)d_in[2];
    const float* bq = (const float*)d_in[3];
    const float* Wk = (const float*)d_in[4];
    const float* bk = (const float*)d_in[5];
    const float* Wv = (const float*)d_in[6];
    const float* bv = (const float*)d_in[7];
    const float* Wo = (const float*)d_in[8];
    const float* bo = (const float*)d_in[9];
    float* out = (float*)d_out;

    cudaFuncSetAttribute(attn_mma, cudaFuncAttributeMaxDynamicSharedMemorySize, SMEM_ATTN);
    cudaFuncSetAttribute(gemm_qkv, cudaFuncAttributeMaxDynamicSharedMemorySize, SMEM_GEMM);
    cudaFuncSetAttribute(gemm_out, cudaFuncAttributeMaxDynamicSharedMemorySize, SMEM_GEMM);

    convert_x<<<(kB * kS * kD / 4) / 256, 256>>>(x);
    convert_w<<<dim3(2048 / 32, kD / 32), 256>>>(Wq, Wk, Wv, Wo);

    gemm_qkv<<<dim3(1280 / 64, (kB * kS) / 128), 256, SMEM_GEMM>>>(bq, bk, bv);

    vsuf_kernel<<<kB * kGH, 256>>>();

    attn_mma<<<dim3(kS / 128, kNH, kB), 256, SMEM_ATTN>>>();

    gemm_out<<<dim3(kD / 64, (kB * kS) / 128), 256, SMEM_GEMM>>>(bo, out);
}

// round 13
// speedup vs baseline: 1.8318x; 1.0702x over previous
#include <cuda_runtime.h>
#include <cuda_fp16.h>
#include <cstdint>

// GroupQuerySelfAttention: B=2, S=2048, D=768, NH=12, GH=4 (rep=3), HD=64
// MASK_FILL = -1e-9 => masked p == exp(-1e-9) == 1.0f exactly. Fully-masked
// key tiles contribute colsum(V-tile) to O (query-independent) and +count to
// lsum => V suffix sums precomputed, ~half the attention tiles skipped.
// R13: vsuf_kernel parallelized (one warp per (bg,hd) row, shfl suffix scan)
// — was 25 us on 8 SMs, now ~2 us. All GEMMs fp16-mma cp.async pipelines.
// Buggy merge == attention out stored [B,NH,HD,S].

namespace {
constexpr int kB  = 2;
constexpr int kS  = 2048;
constexpr int kD  = 768;
constexpr int kNH = 12;
constexpr int kGH = 4;
constexpr int kHD = 64;
constexpr int kREP = 3;
constexpr float kScale = 0.125f;
}

__device__ __half g_Xh [(size_t)kB * kS * kD];
__device__ __half g_WqT[(size_t)kD * kD];
__device__ __half g_WkT[(size_t)(kGH * kHD) * kD];
__device__ __half g_WvT[(size_t)(kGH * kHD) * kD];
__device__ __half g_WoT[(size_t)kD * kD];
__device__ __half g_Qh [(size_t)kB * kNH * kS * kHD];
__device__ __half g_Kh [(size_t)kB * kGH * kS * kHD];
__device__ __half g_Vh [(size_t)kB * kGH * kHD * kS];  // [b, g, hd, s]
__device__ __half g_Oh [(size_t)kB * kNH * kHD * kS];  // [b, h, hd, q]
__device__ float  g_Vsuf[(size_t)kB * kGH * 33 * kHD]; // suffix V tile colsums

// ---------------------------------------------------------------------------
__device__ __forceinline__ void mma_f16(float* d, const uint32_t* a,
                                        uint32_t b0, uint32_t b1) {
    asm volatile(
        "mma.sync.aligned.m16n8k16.row.col.f32.f16.f16.f32 "
        "{%0,%1,%2,%3}, {%4,%5,%6,%7}, {%8,%9}, {%0,%1,%2,%3};"
        : "+f"(d[0]), "+f"(d[1]), "+f"(d[2]), "+f"(d[3])
        : "r"(a[0]), "r"(a[1]), "r"(a[2]), "r"(a[3]), "r"(b0), "r"(b1));
}
__device__ __forceinline__ uint32_t pack_f16(float lo, float hi) {
    uint32_t r;
    asm("cvt.rn.f16x2.f32 %0, %1, %2;" : "=r"(r) : "f"(hi), "f"(lo));
    return r;
}
__device__ __forceinline__ uint32_t smem_u32(const void* p) {
    uint32_t a;
    asm("{ .reg .u64 t; cvta.to.shared.u64 t, %1; cvt.u32.u64 %0, t; }"
        : "=r"(a) : "l"(p));
    return a;
}
__device__ __forceinline__ void cp16(uint32_t dst, const void* src) {
    asm volatile("cp.async.cg.shared.global [%0], [%1], 16;"
                 :: "r"(dst), "l"(src) : "memory");
}
__device__ __forceinline__ void cp_commit() {
    asm volatile("cp.async.commit_group;" ::: "memory");
}
__device__ __forceinline__ void cp_wait1() {
    asm volatile("cp.async.wait_group 1;" ::: "memory");
}
__device__ __forceinline__ uint32_t ld32s(const __half* p) {
    return *reinterpret_cast<const uint32_t*>(p);
}

// ---------------------------------------------------------------------------
// Prep kernels
// ---------------------------------------------------------------------------
__global__ __launch_bounds__(256) void convert_x(const float* __restrict__ x)
{
    const int idx = blockIdx.x * 256 + threadIdx.x;
    float4 v = reinterpret_cast<const float4*>(x)[idx];
    uint2 p;
    p.x = pack_f16(v.x, v.y);
    p.y = pack_f16(v.z, v.w);
    reinterpret_cast<uint2*>(g_Xh)[idx] = p;
}

__global__ __launch_bounds__(256) void convert_w(
    const float* __restrict__ Wq, const float* __restrict__ Wk,
    const float* __restrict__ Wv, const float* __restrict__ Wo)
{
    __shared__ float t[32][33];
    const int c0 = blockIdx.x * 32;
    const int k0 = blockIdx.y * 32;
    const float* W; __half* dst; int Nw, cl;
    if (c0 < 768)       { W = Wq; dst = g_WqT; Nw = 768; cl = c0; }
    else if (c0 < 1024) { W = Wk; dst = g_WkT; Nw = 256; cl = c0 - 768; }
    else if (c0 < 1280) { W = Wv; dst = g_WvT; Nw = 256; cl = c0 - 1024; }
    else                { W = Wo; dst = g_WoT; Nw = 768; cl = c0 - 1280; }
    const int tx = threadIdx.x & 31, ty = threadIdx.x >> 5;
    #pragma unroll
    for (int j = 0; j < 4; ++j)
        t[ty + j * 8][tx] = W[(size_t)(k0 + ty + j * 8) * Nw + cl + tx];
    __syncthreads();
    #pragma unroll
    for (int j = 0; j < 4; ++j) {
        const int n = ty + j * 8;
        dst[(size_t)(cl + n) * kD + k0 + tx] = __float2half_rn(t[tx][n]);
    }
}

// V suffix tile-colsum: g_Vsuf[bg][jt][hd] = sum_{k >= jt*64} V[bg, k, hd].
// One warp per (bg, hd) row: lane t sums tile t (64 keys), then a guarded
// shfl_down suffix scan yields suffix[lane] = sum of tiles >= lane.
// Grid: 64 blocks x 256 thr (8 warps); block covers 8 hd rows of one bg-octant.
__global__ __launch_bounds__(256) void vsuf_kernel()
{
    const int warp = threadIdx.x >> 5, lane = threadIdx.x & 31;
    const int bg = blockIdx.x >> 3;                 // 0..7
    const int hd = (blockIdx.x & 7) * 8 + warp;     // 0..63
    const __half* row = g_Vh + ((size_t)bg * kHD + hd) * kS + lane * 64;

    float s = 0.f;
    #pragma unroll
    for (int i = 0; i < 32; ++i) {
        const uint32_t pk = ld32s(row + 2 * i);
        const __half2 h2 = *reinterpret_cast<const __half2*>(&pk);
        s += __half2float(h2.x) + __half2float(h2.y);
    }
    // inclusive suffix scan across lanes
    #pragma unroll
    for (int off = 1; off < 32; off <<= 1) {
        const float up = __shfl_down_sync(0xffffffffu, s, off);
        if (lane + off < 32) s += up;
    }
    float* dst = g_Vsuf + (size_t)bg * 33 * kHD + hd;
    dst[(size_t)lane * kHD] = s;
    if (lane == 0) dst[(size_t)32 * kHD] = 0.f;
}

// ---------------------------------------------------------------------------
// Pipelined f16 GEMM core (proven R10)
// ---------------------------------------------------------------------------
namespace {
constexpr int GST = 40;
constexpr int GA_B = 128 * GST * 2;
constexpr int GW_B = 64 * GST * 2;
constexpr int GSTAGE_B = GA_B + GW_B;          // 15360 B
constexpr int SMEM_GEMM = 3 * GSTAGE_B;        // 46080 B
constexpr int TPAD = 136;
}

__device__ __forceinline__ void gemm16_mainloop(
    uint32_t sb, const char* smem,
    const __half* __restrict__ Arow, const __half* __restrict__ Wrow,
    int w, int lr, int lc, int tid, float (&acc)[8][4])
{
    auto stage = [&](int ch, int s) {
        const int k0 = ch * 32;
        const uint32_t ab = sb + s * GSTAGE_B;
        const uint32_t wb = ab + GA_B;
        #pragma unroll
        for (int j = 0; j < 2; ++j) {
            const int idx = tid + 256 * j;
            const int r = idx >> 2, c4 = idx & 3;
            cp16(ab + (uint32_t)(r * GST + c4 * 8) * 2,
                 Arow + (size_t)r * kD + k0 + c4 * 8);
        }
        {
            const int r = tid >> 2, c4 = tid & 3;
            cp16(wb + (uint32_t)(r * GST + c4 * 8) * 2,
                 Wrow + (size_t)r * kD + k0 + c4 * 8);
        }
        cp_commit();
    };

    stage(0, 0);
    stage(1, 1);

    const int r0 = w * 16 + lr;
    const int nch = kD / 32;
    int buf = 0;
    for (int ch = 0; ch < nch; ++ch) {
        cp_wait1();
        __syncthreads();
        const __half* Ab = reinterpret_cast<const __half*>(smem + buf * GSTAGE_B);
        const __half* Wb = Ab + 128 * GST;
        #pragma unroll
        for (int ks = 0; ks < 2; ++ks) {
            const int cb = ks * 16 + 2 * lc;
            uint32_t a[4];
            a[0] = ld32s(Ab + r0 * GST + cb);
            a[1] = ld32s(Ab + (r0 + 8) * GST + cb);
            a[2] = ld32s(Ab + r0 * GST + cb + 8);
            a[3] = ld32s(Ab + (r0 + 8) * GST + cb + 8);
            #pragma unroll
            for (int nf = 0; nf < 8; ++nf) {
                const __half* wrow = Wb + (nf * 8 + lr) * GST;
                mma_f16(acc[nf], a, ld32s(wrow + cb), ld32s(wrow + cb + 8));
            }
        }
        if (ch + 2 < nch) stage(ch + 2, (buf + 2) % 3);
        else cp_commit();
        buf = (buf + 1) % 3;
    }
}

__global__ __launch_bounds__(256) void gemm_qkv(
    const float* __restrict__ bq, const float* __restrict__ bk,
    const float* __restrict__ bv)
{
    extern __shared__ char smem[];
    const uint32_t sb = smem_u32(smem);
    const int tid = threadIdx.x;
    const int lane = tid & 31;
    const int w = tid >> 5;
    const int lr = lane >> 2, lc = lane & 3;
    const int rowBase = blockIdx.y * 128;
    const int colBase = blockIdx.x * 64;

    const __half* WT; const float* bias; int colLoc, seg;
    if (colBase < 768)       { WT = g_WqT; bias = bq; colLoc = colBase;        seg = 0; }
    else if (colBase < 1024) { WT = g_WkT; bias = bk; colLoc = colBase - 768;  seg = 1; }
    else                     { WT = g_WvT; bias = bv; colLoc = colBase - 1024; seg = 2; }

    float acc[8][4];
    #pragma unroll
    for (int i = 0; i < 8; ++i)
        #pragma unroll
        for (int j = 0; j < 4; ++j) acc[i][j] = 0.f;

    gemm16_mainloop(sb, smem, g_Xh + (size_t)rowBase * kD,
                    WT + (size_t)colLoc * kD, w, lr, lc, tid, acc);

    const int bb = rowBase / kS;
    const int s0 = rowBase - bb * kS;

    if (seg == 2) {
        __syncthreads();
        __half* T = reinterpret_cast<__half*>(smem);   // [64][TPAD]
        #pragma unroll
        for (int half = 0; half < 2; ++half) {
            const int r = w * 16 + lr + half * 8;
            #pragma unroll
            for (int nf = 0; nf < 8; ++nf) {
                const int c = nf * 8 + 2 * lc;
                T[(c + 0) * TPAD + r] = __float2half_rn(acc[nf][half * 2 + 0] + bias[colLoc + c]);
                T[(c + 1) * TPAD + r] = __float2half_rn(acc[nf][half * 2 + 1] + bias[colLoc + c + 1]);
            }
        }
        __syncthreads();
        const int g = colLoc / kHD;
        __half* base = g_Vh + (size_t)(bb * kGH + g) * kHD * kS;
        #pragma unroll
        for (int j = 0; j < 4; ++j) {
            const int idx = tid + 256 * j;
            const int hd = idx >> 4, ch8 = (idx & 15) * 8;
            uint4 v = *reinterpret_cast<const uint4*>(T + hd * TPAD + ch8);
            *reinterpret_cast<uint4*>(base + (size_t)hd * kS + s0 + ch8) = v;
        }
    } else {
        __half* out = (seg == 0) ? g_Qh : g_Kh;
        const int heads = (seg == 0) ? kNH : kGH;
        #pragma unroll
        for (int half = 0; half < 2; ++half) {
            const int s = s0 + w * 16 + lr + half * 8;
            #pragma unroll
            for (int nf = 0; nf < 8; ++nf) {
                const int c = colLoc + nf * 8 + 2 * lc;
                const int h = c / kHD, cc = c - h * kHD;
                const float v0 = acc[nf][half * 2 + 0] + bias[c];
                const float v1 = acc[nf][half * 2 + 1] + bias[c + 1];
                __half* dst = out + ((size_t)(bb * heads + h) * kS + s) * kHD + cc;
                *reinterpret_cast<uint32_t*>(dst) = pack_f16(v0, v1);
            }
        }
    }
}

__global__ __launch_bounds__(256) void gemm_out(
    const float* __restrict__ bias, float* __restrict__ out)
{
    extern __shared__ char smem[];
    const uint32_t sb = smem_u32(smem);
    const int tid = threadIdx.x;
    const int lane = tid & 31;
    const int w = tid >> 5;
    const int lr = lane >> 2, lc = lane & 3;
    const int rowBase = blockIdx.y * 128;
    const int colBase = blockIdx.x * 64;

    float acc[8][4];
    #pragma unroll
    for (int i = 0; i < 8; ++i)
        #pragma unroll
        for (int j = 0; j < 4; ++j) acc[i][j] = 0.f;

    gemm16_mainloop(sb, smem, g_Oh + (size_t)rowBase * kD,
                    g_WoT + (size_t)colBase * kD, w, lr, lc, tid, acc);

    #pragma unroll
    for (int half = 0; half < 2; ++half) {
        const int r = rowBase + w * 16 + lr + half * 8;
        #pragma unroll
        for (int nf = 0; nf < 8; ++nf) {
            const int c = colBase + nf * 8 + 2 * lc;
            float* dst = out + (size_t)r * kD + c;
            dst[0] = acc[nf][half * 2 + 0] + bias[c];
            dst[1] = acc[nf][half * 2 + 1] + bias[c + 1];
        }
    }
}

// ---------------------------------------------------------------------------
// Attention with masked-tail skipping (kt < ktmax = 2*qt+2), suffix via Vsuf.
// qt reversed so longest CTAs launch first.
// ---------------------------------------------------------------------------
namespace {
constexpr int KST2 = 72;
constexpr int TILE_B = 64 * KST2 * 2;
constexpr int STAGE_B = 2 * TILE_B;
constexpr int SMEM_ATTN = 3 * STAGE_B;         // 55296 B
}

__global__ __launch_bounds__(256, 2) void attn_mma()
{
    extern __shared__ char smem[];
    const uint32_t sb = smem_u32(smem);

    const int tid = threadIdx.x;
    const int lane = tid & 31;
    const int w = tid >> 5;
    const int qt = (int)gridDim.x - 1 - (int)blockIdx.x;   // long CTAs first
    const int h = blockIdx.y, b = blockIdx.z;
    const int g = h / kREP;
    const int lr = lane >> 2, lc = lane & 3;
    const int ktmax = 2 * qt + 2;

    const __half* Qp = g_Qh + ((size_t)(b * kNH + h) * kS + (size_t)qt * 128) * kHD;
    const __half* Kp = g_Kh + (size_t)(b * kGH + g) * kS * kHD;
    const __half* Vp = g_Vh + (size_t)(b * kGH + g) * kHD * kS;

    auto stage_tile = [&](int kt, int s) {
        const __half* Kt = Kp + (size_t)kt * 64 * kHD;
        const __half* Vt = Vp + (size_t)kt * 64;
        const uint32_t kb = sb + s * STAGE_B;
        const uint32_t vb = kb + TILE_B;
        #pragma unroll
        for (int j = 0; j < 2; ++j) {
            const int c = tid + 256 * j;
            const int r = c >> 3, c8 = (c & 7) * 8;
            const uint32_t off = (uint32_t)(r * KST2 + c8) * 2;
            cp16(kb + off, Kt + (size_t)r * kHD + c8);
            cp16(vb + off, Vt + (size_t)r * kS + c8);
        }
        cp_commit();
    };

    stage_tile(0, 0);
    stage_tile(1, 1);

    __half* Qs = reinterpret_cast<__half*>(smem + 2 * STAGE_B);
    #pragma unroll
    for (int j = 0; j < 4; ++j) {
        const int c = tid + 256 * j;
        const int r = c >> 3, c8 = (c & 7) * 8;
        uint4 v = *reinterpret_cast<const uint4*>(Qp + (size_t)r * kHD + c8);
        *reinterpret_cast<uint4*>(Qs + r * KST2 + c8) = v;
    }
    __syncthreads();

    uint32_t qa[4][4];
    {
        const int r0 = w * 16 + lr;
        #pragma unroll
        for (int ks = 0; ks < 4; ++ks) {
            const int cb = ks * 16 + 2 * lc;
            qa[ks][0] = ld32s(Qs + r0 * KST2 + cb);
            qa[ks][1] = ld32s(Qs + (r0 + 8) * KST2 + cb);
            qa[ks][2] = ld32s(Qs + r0 * KST2 + cb + 8);
            qa[ks][3] = ld32s(Qs + (r0 + 8) * KST2 + cb + 8);
        }
    }

    float oacc[8][4];
    #pragma unroll
    for (int i = 0; i < 8; ++i)
        #pragma unroll
        for (int j = 0; j < 4; ++j) oacc[i][j] = 0.f;
    float lsum0 = 0.f, lsum1 = 0.f;
    const int q0 = qt * 128 + w * 16 + lr;

    int buf = 0;
    for (int kt = 0; kt < ktmax; ++kt) {
        cp_wait1();
        __syncthreads();

        const __half* Kb = reinterpret_cast<const __half*>(smem + buf * STAGE_B);
        const __half* Vb = Kb + 64 * KST2;

        #pragma unroll
        for (int sub = 0; sub < 2; ++sub) {
            float sacc[4][4];
            #pragma unroll
            for (int i = 0; i < 4; ++i)
                #pragma unroll
                for (int j = 0; j < 4; ++j) sacc[i][j] = 0.f;

            #pragma unroll
            for (int nf = 0; nf < 4; ++nf) {
                const __half* krow = Kb + (sub * 32 + nf * 8 + lr) * KST2;
                #pragma unroll
                for (int ks = 0; ks < 4; ++ks) {
                    mma_f16(sacc[nf], qa[ks],
                            ld32s(krow + ks * 16 + 2 * lc),
                            ld32s(krow + ks * 16 + 2 * lc + 8));
                }
            }

            uint32_t pa[2][4];
            #pragma unroll
            for (int nf = 0; nf < 4; ++nf) {
                const int colb = kt * 64 + sub * 32 + nf * 8 + 2 * lc;
                const float p0 = (colb     <= q0)     ? __expf(sacc[nf][0] * kScale) : 1.0f;
                const float p1 = (colb + 1 <= q0)     ? __expf(sacc[nf][1] * kScale) : 1.0f;
                const float p2 = (colb     <= q0 + 8) ? __expf(sacc[nf][2] * kScale) : 1.0f;
                const float p3 = (colb + 1 <= q0 + 8) ? __expf(sacc[nf][3] * kScale) : 1.0f;
                lsum0 += p0 + p1;
                lsum1 += p2 + p3;
                const int kk = nf >> 1;
                if ((nf & 1) == 0) {
                    pa[kk][0] = pack_f16(p0, p1);
                    pa[kk][1] = pack_f16(p2, p3);
                } else {
                    pa[kk][2] = pack_f16(p0, p1);
                    pa[kk][3] = pack_f16(p2, p3);
                }
            }

            #pragma unroll
            for (int nd = 0; nd < 8; ++nd) {
                const __half* vrow = Vb + (nd * 8 + lr) * KST2 + sub * 32;
                #pragma unroll
                for (int kk = 0; kk < 2; ++kk) {
                    mma_f16(oacc[nd], pa[kk],
                            ld32s(vrow + kk * 16 + 2 * lc),
                            ld32s(vrow + kk * 16 + 2 * lc + 8));
                }
            }
        }

        if (kt + 2 < ktmax) stage_tile(kt + 2, (buf + 2) % 3);
        else cp_commit();
        buf = (buf + 1) % 3;
    }

    // fully-masked suffix: O += colsum(V[ktmax*64:])
    const float* suf = g_Vsuf + ((size_t)(b * kGH + g) * 33 + ktmax) * kHD;
    #pragma unroll
    for (int nd = 0; nd < 8; ++nd) {
        const int hd = nd * 8 + 2 * lc;
        const float s0v = suf[hd], s1v = suf[hd + 1];
        oacc[nd][0] += s0v; oacc[nd][1] += s1v;
        oacc[nd][2] += s0v; oacc[nd][3] += s1v;
    }

    // quad-reduce processed-range row sums, THEN add tail once
    lsum0 += __shfl_xor_sync(0xffffffffu, lsum0, 1);
    lsum0 += __shfl_xor_sync(0xffffffffu, lsum0, 2);
    lsum1 += __shfl_xor_sync(0xffffffffu, lsum1, 1);
    lsum1 += __shfl_xor_sync(0xffffffffu, lsum1, 2);
    const float tail = (float)(kS - ktmax * 64);
    const float inv0 = 1.f / (lsum0 + tail);
    const float inv1 = 1.f / (lsum1 + tail);

    __half* Op = g_Oh + (size_t)(b * kNH + h) * kHD * kS;
    #pragma unroll
    for (int nd = 0; nd < 8; ++nd) {
        const int hd = nd * 8 + 2 * lc;
        Op[(size_t)hd * kS + q0]           = __float2half_rn(oacc[nd][0] * inv0);
        Op[(size_t)(hd + 1) * kS + q0]     = __float2half_rn(oacc[nd][1] * inv0);
        Op[(size_t)hd * kS + q0 + 8]       = __float2half_rn(oacc[nd][2] * inv1);
        Op[(size_t)(hd + 1) * kS + q0 + 8] = __float2half_rn(oacc[nd][3] * inv1);
    }
}

extern "C" void kernel_launch(void* const* d_in, const int* in_sizes, int n_in,
                              void* d_out, int out_size)
{
    (void)in_sizes; (void)n_in; (void)out_size;
    const float* x  = (const float*)d_in[0];
    const float* Wq = (const float*)d_in[2];
    const float* bq = (const float*)d_in[3];
    const float* Wk = (const float*)d_in[4];
    const float* bk = (const float*)d_in[5];
    const float* Wv = (const float*)d_in[6];
    const float* bv = (const float*)d_in[7];
    const float* Wo = (const float*)d_in[8];
    const float* bo = (const float*)d_in[9];
    float* out = (float*)d_out;

    cudaFuncSetAttribute(attn_mma, cudaFuncAttributeMaxDynamicSharedMemorySize, SMEM_ATTN);
    cudaFuncSetAttribute(gemm_qkv, cudaFuncAttributeMaxDynamicSharedMemorySize, SMEM_GEMM);
    cudaFuncSetAttribute(gemm_out, cudaFuncAttributeMaxDynamicSharedMemorySize, SMEM_GEMM);

    convert_x<<<(kB * kS * kD / 4) / 256, 256>>>(x);
    convert_w<<<dim3(2048 / 32, kD / 32), 256>>>(Wq, Wk, Wv, Wo);

    gemm_qkv<<<dim3(1280 / 64, (kB * kS) / 128), 256, SMEM_GEMM>>>(bq, bk, bv);

    vsuf_kernel<<<64, 256>>>();

    attn_mma<<<dim3(kS / 128, kNH, kB), 256, SMEM_ATTN>>>();

    gemm_out<<<dim3(kD / 64, (kB * kS) / 128), 256, SMEM_GEMM>>>(bo, out);
}

// round 14
// speedup vs baseline: 2.0633x; 1.1263x over previous
#include <cuda_runtime.h>
#include <cuda_fp16.h>
#include <cstdint>

// GroupQuerySelfAttention: B=2, S=2048, D=768, NH=12, GH=4 (rep=3), HD=64
// MASK_FILL = -1e-9 => masked p == exp(-1e-9) == 1.0f exactly. Fully-masked
// key tiles contribute colsum(V-tile) to O and +count to lsum => V suffix
// sums precomputed, ~half the attention tiles skipped.
// R14: global LPT schedule for attn (all long CTAs in wave 1) + vectorized
// vsuf loads. All GEMMs fp16-mma cp.async pipelines.
// Buggy merge == attention out stored [B,NH,HD,S].

namespace {
constexpr int kB  = 2;
constexpr int kS  = 2048;
constexpr int kD  = 768;
constexpr int kNH = 12;
constexpr int kGH = 4;
constexpr int kHD = 64;
constexpr int kREP = 3;
constexpr float kScale = 0.125f;
}

__device__ __half g_Xh [(size_t)kB * kS * kD];
__device__ __half g_WqT[(size_t)kD * kD];
__device__ __half g_WkT[(size_t)(kGH * kHD) * kD];
__device__ __half g_WvT[(size_t)(kGH * kHD) * kD];
__device__ __half g_WoT[(size_t)kD * kD];
__device__ __half g_Qh [(size_t)kB * kNH * kS * kHD];
__device__ __half g_Kh [(size_t)kB * kGH * kS * kHD];
__device__ __half g_Vh [(size_t)kB * kGH * kHD * kS];  // [b, g, hd, s]
__device__ __half g_Oh [(size_t)kB * kNH * kHD * kS];  // [b, h, hd, q]
__device__ float  g_Vsuf[(size_t)kB * kGH * 33 * kHD]; // suffix V tile colsums

// ---------------------------------------------------------------------------
__device__ __forceinline__ void mma_f16(float* d, const uint32_t* a,
                                        uint32_t b0, uint32_t b1) {
    asm volatile(
        "mma.sync.aligned.m16n8k16.row.col.f32.f16.f16.f32 "
        "{%0,%1,%2,%3}, {%4,%5,%6,%7}, {%8,%9}, {%0,%1,%2,%3};"
        : "+f"(d[0]), "+f"(d[1]), "+f"(d[2]), "+f"(d[3])
        : "r"(a[0]), "r"(a[1]), "r"(a[2]), "r"(a[3]), "r"(b0), "r"(b1));
}
__device__ __forceinline__ uint32_t pack_f16(float lo, float hi) {
    uint32_t r;
    asm("cvt.rn.f16x2.f32 %0, %1, %2;" : "=r"(r) : "f"(hi), "f"(lo));
    return r;
}
__device__ __forceinline__ uint32_t smem_u32(const void* p) {
    uint32_t a;
    asm("{ .reg .u64 t; cvta.to.shared.u64 t, %1; cvt.u32.u64 %0, t; }"
        : "=r"(a) : "l"(p));
    return a;
}
__device__ __forceinline__ void cp16(uint32_t dst, const void* src) {
    asm volatile("cp.async.cg.shared.global [%0], [%1], 16;"
                 :: "r"(dst), "l"(src) : "memory");
}
__device__ __forceinline__ void cp_commit() {
    asm volatile("cp.async.commit_group;" ::: "memory");
}
__device__ __forceinline__ void cp_wait1() {
    asm volatile("cp.async.wait_group 1;" ::: "memory");
}
__device__ __forceinline__ uint32_t ld32s(const __half* p) {
    return *reinterpret_cast<const uint32_t*>(p);
}

// ---------------------------------------------------------------------------
// Prep kernels
// ---------------------------------------------------------------------------
__global__ __launch_bounds__(256) void convert_x(const float* __restrict__ x)
{
    const int idx = blockIdx.x * 256 + threadIdx.x;
    float4 v = reinterpret_cast<const float4*>(x)[idx];
    uint2 p;
    p.x = pack_f16(v.x, v.y);
    p.y = pack_f16(v.z, v.w);
    reinterpret_cast<uint2*>(g_Xh)[idx] = p;
}

__global__ __launch_bounds__(256) void convert_w(
    const float* __restrict__ Wq, const float* __restrict__ Wk,
    const float* __restrict__ Wv, const float* __restrict__ Wo)
{
    __shared__ float t[32][33];
    const int c0 = blockIdx.x * 32;
    const int k0 = blockIdx.y * 32;
    const float* W; __half* dst; int Nw, cl;
    if (c0 < 768)       { W = Wq; dst = g_WqT; Nw = 768; cl = c0; }
    else if (c0 < 1024) { W = Wk; dst = g_WkT; Nw = 256; cl = c0 - 768; }
    else if (c0 < 1280) { W = Wv; dst = g_WvT; Nw = 256; cl = c0 - 1024; }
    else                { W = Wo; dst = g_WoT; Nw = 768; cl = c0 - 1280; }
    const int tx = threadIdx.x & 31, ty = threadIdx.x >> 5;
    #pragma unroll
    for (int j = 0; j < 4; ++j)
        t[ty + j * 8][tx] = W[(size_t)(k0 + ty + j * 8) * Nw + cl + tx];
    __syncthreads();
    #pragma unroll
    for (int j = 0; j < 4; ++j) {
        const int n = ty + j * 8;
        dst[(size_t)(cl + n) * kD + k0 + tx] = __float2half_rn(t[tx][n]);
    }
}

// V suffix tile-colsum: one warp per (bg, hd) row; lane t sums tile t via
// 8 x uint4 (16B) loads, then guarded shfl_down suffix scan.
__global__ __launch_bounds__(256) void vsuf_kernel()
{
    const int warp = threadIdx.x >> 5, lane = threadIdx.x & 31;
    const int bg = blockIdx.x >> 3;
    const int hd = (blockIdx.x & 7) * 8 + warp;
    const __half* row = g_Vh + ((size_t)bg * kHD + hd) * kS + lane * 64;

    float s = 0.f;
    #pragma unroll
    for (int i = 0; i < 8; ++i) {
        const uint4 v = *reinterpret_cast<const uint4*>(row + i * 8);
        const __half2* h2 = reinterpret_cast<const __half2*>(&v);
        #pragma unroll
        for (int j = 0; j < 4; ++j) {
            const float2 f = __half22float2(h2[j]);
            s += f.x + f.y;
        }
    }
    #pragma unroll
    for (int off = 1; off < 32; off <<= 1) {
        const float up = __shfl_down_sync(0xffffffffu, s, off);
        if (lane + off < 32) s += up;
    }
    float* dst = g_Vsuf + (size_t)bg * 33 * kHD + hd;
    dst[(size_t)lane * kHD] = s;
    if (lane == 0) dst[(size_t)32 * kHD] = 0.f;
}

// ---------------------------------------------------------------------------
// Pipelined f16 GEMM core (proven R10)
// ---------------------------------------------------------------------------
namespace {
constexpr int GST = 40;
constexpr int GA_B = 128 * GST * 2;
constexpr int GW_B = 64 * GST * 2;
constexpr int GSTAGE_B = GA_B + GW_B;          // 15360 B
constexpr int SMEM_GEMM = 3 * GSTAGE_B;        // 46080 B
constexpr int TPAD = 136;
}

__device__ __forceinline__ void gemm16_mainloop(
    uint32_t sb, const char* smem,
    const __half* __restrict__ Arow, const __half* __restrict__ Wrow,
    int w, int lr, int lc, int tid, float (&acc)[8][4])
{
    auto stage = [&](int ch, int s) {
        const int k0 = ch * 32;
        const uint32_t ab = sb + s * GSTAGE_B;
        const uint32_t wb = ab + GA_B;
        #pragma unroll
        for (int j = 0; j < 2; ++j) {
            const int idx = tid + 256 * j;
            const int r = idx >> 2, c4 = idx & 3;
            cp16(ab + (uint32_t)(r * GST + c4 * 8) * 2,
                 Arow + (size_t)r * kD + k0 + c4 * 8);
        }
        {
            const int r = tid >> 2, c4 = tid & 3;
            cp16(wb + (uint32_t)(r * GST + c4 * 8) * 2,
                 Wrow + (size_t)r * kD + k0 + c4 * 8);
        }
        cp_commit();
    };

    stage(0, 0);
    stage(1, 1);

    const int r0 = w * 16 + lr;
    const int nch = kD / 32;
    int buf = 0;
    for (int ch = 0; ch < nch; ++ch) {
        cp_wait1();
        __syncthreads();
        const __half* Ab = reinterpret_cast<const __half*>(smem + buf * GSTAGE_B);
        const __half* Wb = Ab + 128 * GST;
        #pragma unroll
        for (int ks = 0; ks < 2; ++ks) {
            const int cb = ks * 16 + 2 * lc;
            uint32_t a[4];
            a[0] = ld32s(Ab + r0 * GST + cb);
            a[1] = ld32s(Ab + (r0 + 8) * GST + cb);
            a[2] = ld32s(Ab + r0 * GST + cb + 8);
            a[3] = ld32s(Ab + (r0 + 8) * GST + cb + 8);
            #pragma unroll
            for (int nf = 0; nf < 8; ++nf) {
                const __half* wrow = Wb + (nf * 8 + lr) * GST;
                mma_f16(acc[nf], a, ld32s(wrow + cb), ld32s(wrow + cb + 8));
            }
        }
        if (ch + 2 < nch) stage(ch + 2, (buf + 2) % 3);
        else cp_commit();
        buf = (buf + 1) % 3;
    }
}

__global__ __launch_bounds__(256) void gemm_qkv(
    const float* __restrict__ bq, const float* __restrict__ bk,
    const float* __restrict__ bv)
{
    extern __shared__ char smem[];
    const uint32_t sb = smem_u32(smem);
    const int tid = threadIdx.x;
    const int lane = tid & 31;
    const int w = tid >> 5;
    const int lr = lane >> 2, lc = lane & 3;
    const int rowBase = blockIdx.y * 128;
    const int colBase = blockIdx.x * 64;

    const __half* WT; const float* bias; int colLoc, seg;
    if (colBase < 768)       { WT = g_WqT; bias = bq; colLoc = colBase;        seg = 0; }
    else if (colBase < 1024) { WT = g_WkT; bias = bk; colLoc = colBase - 768;  seg = 1; }
    else                     { WT = g_WvT; bias = bv; colLoc = colBase - 1024; seg = 2; }

    float acc[8][4];
    #pragma unroll
    for (int i = 0; i < 8; ++i)
        #pragma unroll
        for (int j = 0; j < 4; ++j) acc[i][j] = 0.f;

    gemm16_mainloop(sb, smem, g_Xh + (size_t)rowBase * kD,
                    WT + (size_t)colLoc * kD, w, lr, lc, tid, acc);

    const int bb = rowBase / kS;
    const int s0 = rowBase - bb * kS;

    if (seg == 2) {
        __syncthreads();
        __half* T = reinterpret_cast<__half*>(smem);   // [64][TPAD]
        #pragma unroll
        for (int half = 0; half < 2; ++half) {
            const int r = w * 16 + lr + half * 8;
            #pragma unroll
            for (int nf = 0; nf < 8; ++nf) {
                const int c = nf * 8 + 2 * lc;
                T[(c + 0) * TPAD + r] = __float2half_rn(acc[nf][half * 2 + 0] + bias[colLoc + c]);
                T[(c + 1) * TPAD + r] = __float2half_rn(acc[nf][half * 2 + 1] + bias[colLoc + c + 1]);
            }
        }
        __syncthreads();
        const int g = colLoc / kHD;
        __half* base = g_Vh + (size_t)(bb * kGH + g) * kHD * kS;
        #pragma unroll
        for (int j = 0; j < 4; ++j) {
            const int idx = tid + 256 * j;
            const int hd = idx >> 4, ch8 = (idx & 15) * 8;
            uint4 v = *reinterpret_cast<const uint4*>(T + hd * TPAD + ch8);
            *reinterpret_cast<uint4*>(base + (size_t)hd * kS + s0 + ch8) = v;
        }
    } else {
        __half* out = (seg == 0) ? g_Qh : g_Kh;
        const int heads = (seg == 0) ? kNH : kGH;
        #pragma unroll
        for (int half = 0; half < 2; ++half) {
            const int s = s0 + w * 16 + lr + half * 8;
            #pragma unroll
            for (int nf = 0; nf < 8; ++nf) {
                const int c = colLoc + nf * 8 + 2 * lc;
                const int h = c / kHD, cc = c - h * kHD;
                const float v0 = acc[nf][half * 2 + 0] + bias[c];
                const float v1 = acc[nf][half * 2 + 1] + bias[c + 1];
                __half* dst = out + ((size_t)(bb * heads + h) * kS + s) * kHD + cc;
                *reinterpret_cast<uint32_t*>(dst) = pack_f16(v0, v1);
            }
        }
    }
}

__global__ __launch_bounds__(256) void gemm_out(
    const float* __restrict__ bias, float* __restrict__ out)
{
    extern __shared__ char smem[];
    const uint32_t sb = smem_u32(smem);
    const int tid = threadIdx.x;
    const int lane = tid & 31;
    const int w = tid >> 5;
    const int lr = lane >> 2, lc = lane & 3;
    const int rowBase = blockIdx.y * 128;
    const int colBase = blockIdx.x * 64;

    float acc[8][4];
    #pragma unroll
    for (int i = 0; i < 8; ++i)
        #pragma unroll
        for (int j = 0; j < 4; ++j) acc[i][j] = 0.f;

    gemm16_mainloop(sb, smem, g_Oh + (size_t)rowBase * kD,
                    g_WoT + (size_t)colBase * kD, w, lr, lc, tid, acc);

    #pragma unroll
    for (int half = 0; half < 2; ++half) {
        const int r = rowBase + w * 16 + lr + half * 8;
        #pragma unroll
        for (int nf = 0; nf < 8; ++nf) {
            const int c = colBase + nf * 8 + 2 * lc;
            float* dst = out + (size_t)r * kD + c;
            dst[0] = acc[nf][half * 2 + 0] + bias[c];
            dst[1] = acc[nf][half * 2 + 1] + bias[c + 1];
        }
    }
}

// ---------------------------------------------------------------------------
// Attention with masked-tail skipping. 1D grid 384, global LPT order:
// qt = 15 - id/24 (all longest CTAs launch first across the whole grid).
// ---------------------------------------------------------------------------
namespace {
constexpr int KST2 = 72;
constexpr int TILE_B = 64 * KST2 * 2;
constexpr int STAGE_B = 2 * TILE_B;
constexpr int SMEM_ATTN = 3 * STAGE_B;         // 55296 B
}

__global__ __launch_bounds__(256, 2) void attn_mma()
{
    extern __shared__ char smem[];
    const uint32_t sb = smem_u32(smem);

    const int tid = threadIdx.x;
    const int lane = tid & 31;
    const int w = tid >> 5;
    const int id = blockIdx.x;                 // 0..383
    const int qt = 15 - id / 24;               // global LPT: big qt first
    const int pair = id % 24;
    const int h = pair % kNH, b = pair / kNH;
    const int g = h / kREP;
    const int lr = lane >> 2, lc = lane & 3;
    const int ktmax = 2 * qt + 2;

    const __half* Qp = g_Qh + ((size_t)(b * kNH + h) * kS + (size_t)qt * 128) * kHD;
    const __half* Kp = g_Kh + (size_t)(b * kGH + g) * kS * kHD;
    const __half* Vp = g_Vh + (size_t)(b * kGH + g) * kHD * kS;

    auto stage_tile = [&](int kt, int s) {
        const __half* Kt = Kp + (size_t)kt * 64 * kHD;
        const __half* Vt = Vp + (size_t)kt * 64;
        const uint32_t kb = sb + s * STAGE_B;
        const uint32_t vb = kb + TILE_B;
        #pragma unroll
        for (int j = 0; j < 2; ++j) {
            const int c = tid + 256 * j;
            const int r = c >> 3, c8 = (c & 7) * 8;
            const uint32_t off = (uint32_t)(r * KST2 + c8) * 2;
            cp16(kb + off, Kt + (size_t)r * kHD + c8);
            cp16(vb + off, Vt + (size_t)r * kS + c8);
        }
        cp_commit();
    };

    stage_tile(0, 0);
    stage_tile(1, 1);

    __half* Qs = reinterpret_cast<__half*>(smem + 2 * STAGE_B);
    #pragma unroll
    for (int j = 0; j < 4; ++j) {
        const int c = tid + 256 * j;
        const int r = c >> 3, c8 = (c & 7) * 8;
        uint4 v = *reinterpret_cast<const uint4*>(Qp + (size_t)r * kHD + c8);
        *reinterpret_cast<uint4*>(Qs + r * KST2 + c8) = v;
    }
    __syncthreads();

    uint32_t qa[4][4];
    {
        const int r0 = w * 16 + lr;
        #pragma unroll
        for (int ks = 0; ks < 4; ++ks) {
            const int cb = ks * 16 + 2 * lc;
            qa[ks][0] = ld32s(Qs + r0 * KST2 + cb);
            qa[ks][1] = ld32s(Qs + (r0 + 8) * KST2 + cb);
            qa[ks][2] = ld32s(Qs + r0 * KST2 + cb + 8);
            qa[ks][3] = ld32s(Qs + (r0 + 8) * KST2 + cb + 8);
        }
    }

    float oacc[8][4];
    #pragma unroll
    for (int i = 0; i < 8; ++i)
        #pragma unroll
        for (int j = 0; j < 4; ++j) oacc[i][j] = 0.f;
    float lsum0 = 0.f, lsum1 = 0.f;
    const int q0 = qt * 128 + w * 16 + lr;

    int buf = 0;
    for (int kt = 0; kt < ktmax; ++kt) {
        cp_wait1();
        __syncthreads();

        const __half* Kb = reinterpret_cast<const __half*>(smem + buf * STAGE_B);
        const __half* Vb = Kb + 64 * KST2;

        #pragma unroll
        for (int sub = 0; sub < 2; ++sub) {
            float sacc[4][4];
            #pragma unroll
            for (int i = 0; i < 4; ++i)
                #pragma unroll
                for (int j = 0; j < 4; ++j) sacc[i][j] = 0.f;

            #pragma unroll
            for (int nf = 0; nf < 4; ++nf) {
                const __half* krow = Kb + (sub * 32 + nf * 8 + lr) * KST2;
                #pragma unroll
                for (int ks = 0; ks < 4; ++ks) {
                    mma_f16(sacc[nf], qa[ks],
                            ld32s(krow + ks * 16 + 2 * lc),
                            ld32s(krow + ks * 16 + 2 * lc + 8));
                }
            }

            uint32_t pa[2][4];
            #pragma unroll
            for (int nf = 0; nf < 4; ++nf) {
                const int colb = kt * 64 + sub * 32 + nf * 8 + 2 * lc;
                const float p0 = (colb     <= q0)     ? __expf(sacc[nf][0] * kScale) : 1.0f;
                const float p1 = (colb + 1 <= q0)     ? __expf(sacc[nf][1] * kScale) : 1.0f;
                const float p2 = (colb     <= q0 + 8) ? __expf(sacc[nf][2] * kScale) : 1.0f;
                const float p3 = (colb + 1 <= q0 + 8) ? __expf(sacc[nf][3] * kScale) : 1.0f;
                lsum0 += p0 + p1;
                lsum1 += p2 + p3;
                const int kk = nf >> 1;
                if ((nf & 1) == 0) {
                    pa[kk][0] = pack_f16(p0, p1);
                    pa[kk][1] = pack_f16(p2, p3);
                } else {
                    pa[kk][2] = pack_f16(p0, p1);
                    pa[kk][3] = pack_f16(p2, p3);
                }
            }

            #pragma unroll
            for (int nd = 0; nd < 8; ++nd) {
                const __half* vrow = Vb + (nd * 8 + lr) * KST2 + sub * 32;
                #pragma unroll
                for (int kk = 0; kk < 2; ++kk) {
                    mma_f16(oacc[nd], pa[kk],
                            ld32s(vrow + kk * 16 + 2 * lc),
                            ld32s(vrow + kk * 16 + 2 * lc + 8));
                }
            }
        }

        if (kt + 2 < ktmax) stage_tile(kt + 2, (buf + 2) % 3);
        else cp_commit();
        buf = (buf + 1) % 3;
    }

    // fully-masked suffix: O += colsum(V[ktmax*64:])
    const float* suf = g_Vsuf + ((size_t)(b * kGH + g) * 33 + ktmax) * kHD;
    #pragma unroll
    for (int nd = 0; nd < 8; ++nd) {
        const int hd = nd * 8 + 2 * lc;
        const float s0v = suf[hd], s1v = suf[hd + 1];
        oacc[nd][0] += s0v; oacc[nd][1] += s1v;
        oacc[nd][2] += s0v; oacc[nd][3] += s1v;
    }

    // quad-reduce processed-range row sums, THEN add tail once
    lsum0 += __shfl_xor_sync(0xffffffffu, lsum0, 1);
    lsum0 += __shfl_xor_sync(0xffffffffu, lsum0, 2);
    lsum1 += __shfl_xor_sync(0xffffffffu, lsum1, 1);
    lsum1 += __shfl_xor_sync(0xffffffffu, lsum1, 2);
    const float tail = (float)(kS - ktmax * 64);
    const float inv0 = 1.f / (lsum0 + tail);
    const float inv1 = 1.f / (lsum1 + tail);

    __half* Op = g_Oh + (size_t)(b * kNH + h) * kHD * kS;
    #pragma unroll
    for (int nd = 0; nd < 8; ++nd) {
        const int hd = nd * 8 + 2 * lc;
        Op[(size_t)hd * kS + q0]           = __float2half_rn(oacc[nd][0] * inv0);
        Op[(size_t)(hd + 1) * kS + q0]     = __float2half_rn(oacc[nd][1] * inv0);
        Op[(size_t)hd * kS + q0 + 8]       = __float2half_rn(oacc[nd][2] * inv1);
        Op[(size_t)(hd + 1) * kS + q0 + 8] = __float2half_rn(oacc[nd][3] * inv1);
    }
}

extern "C" void kernel_launch(void* const* d_in, const int* in_sizes, int n_in,
                              void* d_out, int out_size)
{
    (void)in_sizes; (void)n_in; (void)out_size;
    const float* x  = (const float*)d_in[0];
    const float* Wq = (const float*)d_in[2];
    const float* bq = (const float*)d_in[3];
    const float* Wk = (const float*)d_in[4];
    const float* bk = (const float*)d_in[5];
    const float* Wv = (const float*)d_in[6];
    const float* bv = (const float*)d_in[7];
    const float* Wo = (const float*)d_in[8];
    const float* bo = (const float*)d_in[9];
    float* out = (float*)d_out;

    cudaFuncSetAttribute(attn_mma, cudaFuncAttributeMaxDynamicSharedMemorySize, SMEM_ATTN);
    cudaFuncSetAttribute(gemm_qkv, cudaFuncAttributeMaxDynamicSharedMemorySize, SMEM_GEMM);
    cudaFuncSetAttribute(gemm_out, cudaFuncAttributeMaxDynamicSharedMemorySize, SMEM_GEMM);

    convert_x<<<(kB * kS * kD / 4) / 256, 256>>>(x);
    convert_w<<<dim3(2048 / 32, kD / 32), 256>>>(Wq, Wk, Wv, Wo);

    gemm_qkv<<<dim3(1280 / 64, (kB * kS) / 128), 256, SMEM_GEMM>>>(bq, bk, bv);

    vsuf_kernel<<<64, 256>>>();

    attn_mma<<<kS / 128 * kNH * kB, 256, SMEM_ATTN>>>();

    gemm_out<<<dim3(kD / 64, (kB * kS) / 128), 256, SMEM_GEMM>>>(bo, out);
}